// round 1
// baseline (speedup 1.0000x reference)
#include <cuda_runtime.h>
#include <math.h>

#define N_NODES 50000
#define N_EDGES 800000
#define ETOT    850000   // edges + self loops
#define F_IN    128
#define HID     64
#define HEADS   4
#define DDIM    256      // HID*HEADS
#define OUTF    40
#define NGRP    8
#define EPS_LN  1e-5f

// ---------------- scratch (device globals; no dynamic alloc allowed) ----------------
__device__ float g_bufA[(size_t)N_NODES * DDIM];
__device__ float g_bufB[(size_t)N_NODES * DDIM];
__device__ float g_proj[(size_t)N_NODES * DDIM];
__device__ float g_als[N_NODES * HEADS];
__device__ float g_ald[N_NODES * HEADS];
__device__ float g_m[N_NODES * HEADS];
__device__ float g_s[N_NODES * HEADS];
__device__ float g_ew[(size_t)ETOT * HEADS];
__device__ float g_sums[NGRP * DDIM];
__device__ float g_cnt[NGRP];

// ---------------- helpers ----------------
__device__ __forceinline__ void atomicMaxF(float* a, float v) {
    if (v >= 0.0f) atomicMax((int*)a, __float_as_int(v));
    else           atomicMin((unsigned int*)a, __float_as_uint(v));
}

__device__ __forceinline__ void red_add_v4(float4* addr, float4 v) {
    asm volatile("red.global.add.v4.f32 [%0], {%1,%2,%3,%4};"
                 :: "l"(addr), "f"(v.x), "f"(v.y), "f"(v.z), "f"(v.w)
                 : "memory");
}

// ---------------- encoder: Linear(128->64) -> LN -> ReLU -> Linear(64->64) ----------------
__global__ void encoder_kernel(const float* __restrict__ x,
                               const float* __restrict__ w1, const float* __restrict__ b1,
                               const float* __restrict__ gam, const float* __restrict__ bet,
                               const float* __restrict__ w2, const float* __restrict__ b2,
                               float* __restrict__ h0) {
    int n = blockIdx.x;
    int t = threadIdx.x;           // 64 threads
    __shared__ float xs[128];
    __shared__ float y[64];
    xs[t]      = x[(size_t)n * 128 + t];
    xs[t + 64] = x[(size_t)n * 128 + 64 + t];
    __syncthreads();
    float acc = b1[t];
#pragma unroll 8
    for (int k = 0; k < 128; k++) acc += xs[k] * w1[k * 64 + t];
    y[t] = acc;
    __syncthreads();
    float m = 0.0f;
#pragma unroll 8
    for (int k = 0; k < 64; k++) m += y[k];
    m *= (1.0f / 64.0f);
    float v = 0.0f;
#pragma unroll 8
    for (int k = 0; k < 64; k++) { float d = y[k] - m; v += d * d; }
    v *= (1.0f / 64.0f);
    float z = fmaxf(0.0f, gam[t] * (acc - m) * rsqrtf(v + EPS_LN) + bet[t]);
    __syncthreads();
    y[t] = z;
    __syncthreads();
    float o = b2[t];
#pragma unroll 8
    for (int k = 0; k < 64; k++) o += y[k] * w2[k * 64 + t];
    h0[(size_t)n * 64 + t] = o;
}

// ---------------- tiled fp32 GEMM: C[M,256] = A[M,K] @ B[K,256] ----------------
#define BM 64
#define BN 64
#define BK 16
__global__ __launch_bounds__(256) void gemm_kernel(const float* __restrict__ A,
                                                   const float* __restrict__ B,
                                                   float* __restrict__ C,
                                                   int M, int K) {
    __shared__ float As[BK][BM + 4];
    __shared__ float Bs[BK][BN];
    int t = threadIdx.x;
    int bm0 = blockIdx.y * BM;
    int bn0 = blockIdx.x * BN;
    int tx = t & 15, ty = t >> 4;
    float acc[4][4] = {};
    int arow = t >> 2;
    int acol4 = t & 3;
    int brow = t >> 4;
    int bcol4 = t & 15;
    for (int k0 = 0; k0 < K; k0 += BK) {
        int gr = bm0 + arow;
        float4 av = make_float4(0.f, 0.f, 0.f, 0.f);
        if (gr < M) av = *(const float4*)(A + (size_t)gr * K + k0 + acol4 * 4);
        As[acol4 * 4 + 0][arow] = av.x;
        As[acol4 * 4 + 1][arow] = av.y;
        As[acol4 * 4 + 2][arow] = av.z;
        As[acol4 * 4 + 3][arow] = av.w;
        float4 bv = *(const float4*)(B + (size_t)(k0 + brow) * DDIM + bn0 + bcol4 * 4);
        *(float4*)(&Bs[brow][bcol4 * 4]) = bv;
        __syncthreads();
#pragma unroll
        for (int k = 0; k < BK; k++) {
            float a[4], b[4];
#pragma unroll
            for (int i = 0; i < 4; i++) a[i] = As[k][ty * 4 + i];
#pragma unroll
            for (int j = 0; j < 4; j++) b[j] = Bs[k][tx * 4 + j];
#pragma unroll
            for (int i = 0; i < 4; i++)
#pragma unroll
                for (int j = 0; j < 4; j++) acc[i][j] += a[i] * b[j];
        }
        __syncthreads();
    }
#pragma unroll
    for (int i = 0; i < 4; i++) {
        int row = bm0 + ty * 4 + i;
        if (row < M) {
#pragma unroll
            for (int j = 0; j < 4; j++)
                C[(size_t)row * DDIM + bn0 + tx * 4 + j] = acc[i][j];
        }
    }
}

// ---------------- attention coefficients: al_s/al_d [N,H] ----------------
__global__ void attcoef_kernel(const float* __restrict__ hp,
                               const float* __restrict__ a_s,
                               const float* __restrict__ a_d,
                               float* __restrict__ als, float* __restrict__ ald) {
    int w = (blockIdx.x * blockDim.x + threadIdx.x) >> 5;
    int lane = threadIdx.x & 31;
    if (w >= N_NODES) return;
    const float* row = hp + (size_t)w * DDIM;
#pragma unroll
    for (int h = 0; h < HEADS; h++) {
        float v1 = row[h * 64 + lane];
        float v2 = row[h * 64 + 32 + lane];
        float ps = v1 * a_s[h * 64 + lane] + v2 * a_s[h * 64 + 32 + lane];
        float pd = v1 * a_d[h * 64 + lane] + v2 * a_d[h * 64 + 32 + lane];
#pragma unroll
        for (int o = 16; o; o >>= 1) {
            ps += __shfl_xor_sync(0xFFFFFFFFu, ps, o);
            pd += __shfl_xor_sync(0xFFFFFFFFu, pd, o);
        }
        if (lane == 0) { als[w * HEADS + h] = ps; ald[w * HEADS + h] = pd; }
    }
}

// ---------------- init m=-inf, s=0 ----------------
__global__ void init_ms_kernel(float* __restrict__ m, float* __restrict__ s) {
    int i = blockIdx.x * blockDim.x + threadIdx.x;
    if (i < N_NODES * HEADS) { m[i] = -INFINITY; s[i] = 0.0f; }
}

// ---------------- edge pass 1: logits + segment max ----------------
__global__ void edge_logits_kernel(const int* __restrict__ ei,
                                   const float* __restrict__ als, const float* __restrict__ ald,
                                   float* __restrict__ ew, float* __restrict__ m) {
    int e = blockIdx.x * blockDim.x + threadIdx.x;
    if (e >= ETOT) return;
    int src, dst;
    if (e < N_EDGES) { src = ei[e]; dst = ei[N_EDGES + e]; }
    else             { src = dst = e - N_EDGES; }
    float4 a = ((const float4*)als)[src];
    float4 b = ((const float4*)ald)[dst];
    float4 v;
    v.x = a.x + b.x; v.x = v.x > 0.f ? v.x : 0.2f * v.x;
    v.y = a.y + b.y; v.y = v.y > 0.f ? v.y : 0.2f * v.y;
    v.z = a.z + b.z; v.z = v.z > 0.f ? v.z : 0.2f * v.z;
    v.w = a.w + b.w; v.w = v.w > 0.f ? v.w : 0.2f * v.w;
    ((float4*)ew)[e] = v;
    atomicMaxF(m + dst * 4 + 0, v.x);
    atomicMaxF(m + dst * 4 + 1, v.y);
    atomicMaxF(m + dst * 4 + 2, v.z);
    atomicMaxF(m + dst * 4 + 3, v.w);
}

// ---------------- edge pass 2: exp + segment sum ----------------
__global__ void edge_exp_kernel(const int* __restrict__ ei,
                                float* __restrict__ ew,
                                const float* __restrict__ m, float* __restrict__ s) {
    int e = blockIdx.x * blockDim.x + threadIdx.x;
    if (e >= ETOT) return;
    int dst;
    if (e < N_EDGES) dst = ei[N_EDGES + e];
    else             dst = e - N_EDGES;
    float4 v = ((const float4*)ew)[e];
    float4 mm = ((const float4*)m)[dst];
    float4 w;
    w.x = expf(v.x - mm.x);
    w.y = expf(v.y - mm.y);
    w.z = expf(v.z - mm.z);
    w.w = expf(v.w - mm.w);
    ((float4*)ew)[e] = w;
    red_add_v4(((float4*)s) + dst, w);
}

// ---------------- edge pass 3: weighted aggregation (warp per edge) ----------------
__global__ void edge_aggr_kernel(const int* __restrict__ ei,
                                 const float* __restrict__ hp,
                                 const float* __restrict__ ew,
                                 const float* __restrict__ s,
                                 float* __restrict__ hout) {
    int w = (int)((blockIdx.x * (unsigned)blockDim.x + threadIdx.x) >> 5);
    int lane = threadIdx.x & 31;
    if (w >= ETOT) return;
    int src, dst;
    if (w < N_EDGES) { src = ei[w]; dst = ei[N_EDGES + w]; }
    else             { src = dst = w - N_EDGES; }
    const float4* hs = (const float4*)(hp + (size_t)src * DDIM);
    float4* hd = (float4*)(hout + (size_t)dst * DDIM);
#pragma unroll
    for (int half = 0; half < 2; half++) {
        int c4 = lane + half * 32;     // float4 index within the 256-wide row
        int h = c4 >> 4;               // 16 float4 per head
        float alpha = ew[(size_t)w * HEADS + h] / (s[dst * HEADS + h] + 1e-16f);
        float4 v = hs[c4];
        v.x *= alpha; v.y *= alpha; v.z *= alpha; v.w *= alpha;
        red_add_v4(hd + c4, v);
    }
}

// ---------------- bias + ELU (in place) ----------------
__global__ void bias_elu_kernel(float* __restrict__ h, const float* __restrict__ bias) {
    size_t i = (size_t)blockIdx.x * blockDim.x + threadIdx.x;
    if (i >= (size_t)N_NODES * (DDIM / 4)) return;
    float4 v = ((float4*)h)[i];
    float4 b = ((const float4*)bias)[i & 63];
    v.x += b.x; v.y += b.y; v.z += b.z; v.w += b.w;
    v.x = v.x > 0.f ? v.x : expm1f(v.x);
    v.y = v.y > 0.f ? v.y : expm1f(v.y);
    v.z = v.z > 0.f ? v.z : expm1f(v.z);
    v.w = v.w > 0.f ? v.w : expm1f(v.w);
    ((float4*)h)[i] = v;
}

// ---------------- mean pool over sorted batch ----------------
#define PCHUNK 256
__global__ void pool_kernel(const float* __restrict__ h, const int* __restrict__ batch,
                            float* __restrict__ sums, float* __restrict__ cnt) {
    __shared__ int sb[PCHUNK];
    int n0 = blockIdx.x * PCHUNK;
    int n1 = min(N_NODES, n0 + PCHUNK);
    int cnt_local = n1 - n0;
    for (int i = threadIdx.x; i < cnt_local; i += blockDim.x) sb[i] = batch[n0 + i];
    __syncthreads();
    int t = threadIdx.x;     // feature index, 256 threads
    float acc = 0.0f;
    int gp = sb[0];
    for (int i = 0; i < cnt_local; i++) {
        int g = sb[i];
        if (g != gp) { atomicAdd(&sums[gp * DDIM + t], acc); acc = 0.0f; gp = g; }
        acc += h[(size_t)(n0 + i) * DDIM + t];
    }
    atomicAdd(&sums[gp * DDIM + t], acc);
    if (t == 0) {
        float c = 0.0f; gp = sb[0];
        for (int i = 0; i < cnt_local; i++) {
            int g = sb[i];
            if (g != gp) { atomicAdd(&cnt[gp], c); c = 0.0f; gp = g; }
            c += 1.0f;
        }
        atomicAdd(&cnt[gp], c);
    }
}

// ---------------- decoder: mean -> Linear -> LN -> ReLU -> Linear ----------------
__global__ void decoder_kernel(const float* __restrict__ sums, const float* __restrict__ cnt,
                               const float* __restrict__ w1, const float* __restrict__ b1,
                               const float* __restrict__ gam, const float* __restrict__ bet,
                               const float* __restrict__ w2, const float* __restrict__ b2,
                               float* __restrict__ out) {
    __shared__ float p[DDIM];
    __shared__ float y[64];
    int t = threadIdx.x;     // 64 threads
    for (int gr = 0; gr < NGRP; gr++) {
        float invc = 1.0f / fmaxf(cnt[gr], 1.0f);
        for (int i = t; i < DDIM; i += 64) p[i] = sums[gr * DDIM + i] * invc;
        __syncthreads();
        float acc = b1[t];
        for (int k = 0; k < DDIM; k++) acc += p[k] * w1[k * 64 + t];
        y[t] = acc;
        __syncthreads();
        float m = 0.0f;
        for (int k = 0; k < 64; k++) m += y[k];
        m *= (1.0f / 64.0f);
        float v = 0.0f;
        for (int k = 0; k < 64; k++) { float d = y[k] - m; v += d * d; }
        v *= (1.0f / 64.0f);
        float z = fmaxf(0.0f, gam[t] * (acc - m) * rsqrtf(v + EPS_LN) + bet[t]);
        __syncthreads();
        y[t] = z;
        __syncthreads();
        if (t < OUTF) {
            float o = b2[t];
            for (int k = 0; k < 64; k++) o += y[k] * w2[k * OUTF + t];
            out[gr * OUTF + t] = o;
        }
        __syncthreads();
    }
}

// ---------------- orchestration ----------------
extern "C" void kernel_launch(void* const* d_in, const int* in_sizes, int n_in,
                              void* d_out, int out_size) {
    const float* x      = (const float*)d_in[0];
    const int*   ei     = (const int*)d_in[1];
    const int*   batch  = (const int*)d_in[2];
    const float* enc_w1 = (const float*)d_in[3];
    const float* enc_b1 = (const float*)d_in[4];
    const float* enc_g  = (const float*)d_in[5];
    const float* enc_be = (const float*)d_in[6];
    const float* enc_w2 = (const float*)d_in[7];
    const float* enc_b2 = (const float*)d_in[8];
    const float* convW[3]  = { (const float*)d_in[9],  (const float*)d_in[13], (const float*)d_in[17] };
    const float* convAS[3] = { (const float*)d_in[10], (const float*)d_in[14], (const float*)d_in[18] };
    const float* convAD[3] = { (const float*)d_in[11], (const float*)d_in[15], (const float*)d_in[19] };
    const float* convB[3]  = { (const float*)d_in[12], (const float*)d_in[16], (const float*)d_in[20] };
    const float* dec_w1 = (const float*)d_in[21];
    const float* dec_b1 = (const float*)d_in[22];
    const float* dec_g  = (const float*)d_in[23];
    const float* dec_be = (const float*)d_in[24];
    const float* dec_w2 = (const float*)d_in[25];
    const float* dec_b2 = (const float*)d_in[26];

    float *bufA, *bufB, *proj, *als, *ald, *mb, *sb, *ew, *sums, *cnt;
    cudaGetSymbolAddress((void**)&bufA, g_bufA);
    cudaGetSymbolAddress((void**)&bufB, g_bufB);
    cudaGetSymbolAddress((void**)&proj, g_proj);
    cudaGetSymbolAddress((void**)&als,  g_als);
    cudaGetSymbolAddress((void**)&ald,  g_ald);
    cudaGetSymbolAddress((void**)&mb,   g_m);
    cudaGetSymbolAddress((void**)&sb,   g_s);
    cudaGetSymbolAddress((void**)&ew,   g_ew);
    cudaGetSymbolAddress((void**)&sums, g_sums);
    cudaGetSymbolAddress((void**)&cnt,  g_cnt);

    // encoder -> bufA as [N,64]
    encoder_kernel<<<N_NODES, 64>>>(x, enc_w1, enc_b1, enc_g, enc_be, enc_w2, enc_b2, bufA);

    float* hin = bufA;
    float* hout = bufB;
    int Fin = HID;
    for (int L = 0; L < 3; L++) {
        dim3 ggrid(DDIM / BN, (N_NODES + BM - 1) / BM);
        gemm_kernel<<<ggrid, 256>>>(hin, convW[L], proj, N_NODES, Fin);
        attcoef_kernel<<<(N_NODES * 32 + 255) / 256, 256>>>(proj, convAS[L], convAD[L], als, ald);
        init_ms_kernel<<<(N_NODES * HEADS + 255) / 256, 256>>>(mb, sb);
        cudaMemsetAsync(hout, 0, (size_t)N_NODES * DDIM * sizeof(float));
        edge_logits_kernel<<<(ETOT + 255) / 256, 256>>>(ei, als, ald, ew, mb);
        edge_exp_kernel<<<(ETOT + 255) / 256, 256>>>(ei, ew, mb, sb);
        edge_aggr_kernel<<<(int)(((size_t)ETOT * 32 + 255) / 256), 256>>>(ei, proj, ew, sb, hout);
        bias_elu_kernel<<<(N_NODES * (DDIM / 4) + 255) / 256, 256>>>(hout, convB[L]);
        float* tmp = hin; hin = hout; hout = tmp;
        Fin = DDIM;
    }

    cudaMemsetAsync(sums, 0, NGRP * DDIM * sizeof(float));
    cudaMemsetAsync(cnt, 0, NGRP * sizeof(float));
    pool_kernel<<<(N_NODES + PCHUNK - 1) / PCHUNK, 256>>>(hin, batch, sums, cnt);
    decoder_kernel<<<1, 64>>>(sums, cnt, dec_w1, dec_b1, dec_g, dec_be, dec_w2, dec_b2,
                              (float*)d_out);
}

// round 2
// speedup vs baseline: 1.3909x; 1.3909x over previous
#include <cuda_runtime.h>
#include <math.h>

#define N_NODES 50000
#define N_EDGES 800000
#define ETOT    850000   // edges + self loops
#define F_IN    128
#define HID     64
#define HEADS   4
#define DDIM    256      // HID*HEADS
#define OUTF    40
#define NGRP    8
#define EPS_LN  1e-5f
#define CAP     96       // per-node smem edge cache (max degree ~36 expected)

// ---------------- scratch (device globals; no dynamic alloc allowed) ----------------
__device__ float g_bufA[(size_t)N_NODES * DDIM];
__device__ float g_bufB[(size_t)N_NODES * DDIM];
__device__ float g_proj[(size_t)N_NODES * DDIM];
__device__ float g_als[N_NODES * HEADS];
__device__ float g_ald[N_NODES * HEADS];
__device__ int   g_deg[N_NODES];
__device__ int   g_off[N_NODES + 1];
__device__ int   g_cur[N_NODES];
__device__ int   g_adj[ETOT];
__device__ float g_sums[NGRP * DDIM];
__device__ float g_cnt[NGRP];

// ---------------- encoder: Linear(128->64) -> LN -> ReLU -> Linear(64->64) ----------------
__global__ void encoder_kernel(const float* __restrict__ x,
                               const float* __restrict__ w1, const float* __restrict__ b1,
                               const float* __restrict__ gam, const float* __restrict__ bet,
                               const float* __restrict__ w2, const float* __restrict__ b2,
                               float* __restrict__ h0) {
    int n = blockIdx.x;
    int t = threadIdx.x;           // 64 threads
    __shared__ float xs[128];
    __shared__ float y[64];
    xs[t]      = x[(size_t)n * 128 + t];
    xs[t + 64] = x[(size_t)n * 128 + 64 + t];
    __syncthreads();
    float acc = b1[t];
#pragma unroll 8
    for (int k = 0; k < 128; k++) acc += xs[k] * w1[k * 64 + t];
    y[t] = acc;
    __syncthreads();
    float m = 0.0f;
#pragma unroll 8
    for (int k = 0; k < 64; k++) m += y[k];
    m *= (1.0f / 64.0f);
    float v = 0.0f;
#pragma unroll 8
    for (int k = 0; k < 64; k++) { float d = y[k] - m; v += d * d; }
    v *= (1.0f / 64.0f);
    float z = fmaxf(0.0f, gam[t] * (acc - m) * rsqrtf(v + EPS_LN) + bet[t]);
    __syncthreads();
    y[t] = z;
    __syncthreads();
    float o = b2[t];
#pragma unroll 8
    for (int k = 0; k < 64; k++) o += y[k] * w2[k * 64 + t];
    h0[(size_t)n * 64 + t] = o;
}

// ---------------- 128x128x8 fp32 GEMM, 8x8 microtiles: C[M,256] = A[M,K] @ B[K,256] ----------------
#define GBM 128
#define GBN 128
#define GBK 8
__global__ __launch_bounds__(256) void sgemm128_kernel(const float* __restrict__ A,
                                                       const float* __restrict__ B,
                                                       float* __restrict__ C,
                                                       int M, int K) {
    __shared__ float As[GBK][GBM + 4];
    __shared__ float Bs[GBK][GBN];
    int t = threadIdx.x;
    int bm0 = blockIdx.y * GBM;
    int bn0 = blockIdx.x * GBN;
    int tx = t & 15, ty = t >> 4;          // 16x16 threads, each 8x8 outputs
    int arow = t >> 1;                     // 0..127
    int acol = (t & 1) * 4;                // 0 or 4
    int brow = t >> 5;                     // 0..7
    int bcol = (t & 31) * 4;               // 0..124
    float acc[8][8] = {};
    for (int k0 = 0; k0 < K; k0 += GBK) {
        int gr = bm0 + arow;
        float4 av = make_float4(0.f, 0.f, 0.f, 0.f);
        if (gr < M) av = *(const float4*)(A + (size_t)gr * K + k0 + acol);
        As[acol + 0][arow] = av.x;
        As[acol + 1][arow] = av.y;
        As[acol + 2][arow] = av.z;
        As[acol + 3][arow] = av.w;
        float4 bv = *(const float4*)(B + (size_t)(k0 + brow) * DDIM + bn0 + bcol);
        *(float4*)(&Bs[brow][bcol]) = bv;
        __syncthreads();
#pragma unroll
        for (int k = 0; k < GBK; k++) {
            float a[8], b[8];
            *(float4*)(a)     = *(const float4*)(&As[k][ty * 8]);
            *(float4*)(a + 4) = *(const float4*)(&As[k][ty * 8 + 4]);
            *(float4*)(b)     = *(const float4*)(&Bs[k][tx * 8]);
            *(float4*)(b + 4) = *(const float4*)(&Bs[k][tx * 8 + 4]);
#pragma unroll
            for (int i = 0; i < 8; i++)
#pragma unroll
                for (int j = 0; j < 8; j++) acc[i][j] += a[i] * b[j];
        }
        __syncthreads();
    }
#pragma unroll
    for (int i = 0; i < 8; i++) {
        int row = bm0 + ty * 8 + i;
        if (row < M) {
            float* cp = C + (size_t)row * DDIM + bn0 + tx * 8;
            *(float4*)(cp)     = make_float4(acc[i][0], acc[i][1], acc[i][2], acc[i][3]);
            *(float4*)(cp + 4) = make_float4(acc[i][4], acc[i][5], acc[i][6], acc[i][7]);
        }
    }
}

// ---------------- attention coefficients: al_s/al_d [N,H] ----------------
__global__ void attcoef_kernel(const float* __restrict__ hp,
                               const float* __restrict__ a_s,
                               const float* __restrict__ a_d,
                               float* __restrict__ als, float* __restrict__ ald) {
    int w = (blockIdx.x * blockDim.x + threadIdx.x) >> 5;
    int lane = threadIdx.x & 31;
    if (w >= N_NODES) return;
    const float* row = hp + (size_t)w * DDIM;
#pragma unroll
    for (int h = 0; h < HEADS; h++) {
        float v1 = row[h * 64 + lane];
        float v2 = row[h * 64 + 32 + lane];
        float ps = v1 * a_s[h * 64 + lane] + v2 * a_s[h * 64 + 32 + lane];
        float pd = v1 * a_d[h * 64 + lane] + v2 * a_d[h * 64 + 32 + lane];
#pragma unroll
        for (int o = 16; o; o >>= 1) {
            ps += __shfl_xor_sync(0xFFFFFFFFu, ps, o);
            pd += __shfl_xor_sync(0xFFFFFFFFu, pd, o);
        }
        if (lane == 0) { als[w * HEADS + h] = ps; ald[w * HEADS + h] = pd; }
    }
}

// ---------------- CSR build ----------------
__global__ void hist_kernel(const int* __restrict__ ei, int* __restrict__ deg) {
    int e = blockIdx.x * blockDim.x + threadIdx.x;
    if (e >= ETOT) return;
    int dst = (e < N_EDGES) ? ei[N_EDGES + e] : (e - N_EDGES);
    atomicAdd(&deg[dst], 1);
}

#define SCAN_T 1024
__global__ void scan_kernel(const int* __restrict__ deg,
                            int* __restrict__ off, int* __restrict__ cur) {
    __shared__ int sm[SCAN_T];
    __shared__ int carry;
    int t = threadIdx.x;
    if (t == 0) carry = 0;
    __syncthreads();
    for (int base = 0; base < N_NODES; base += SCAN_T) {
        int i = base + t;
        int v = (i < N_NODES) ? deg[i] : 0;
        sm[t] = v;
        __syncthreads();
        for (int o = 1; o < SCAN_T; o <<= 1) {
            int add = (t >= o) ? sm[t - o] : 0;
            __syncthreads();
            sm[t] += add;
            __syncthreads();
        }
        int excl = ((t == 0) ? 0 : sm[t - 1]) + carry;
        if (i < N_NODES) { off[i] = excl; cur[i] = excl; }
        __syncthreads();
        if (t == 0) carry += sm[SCAN_T - 1];
        __syncthreads();
    }
    if (t == 0) off[N_NODES] = carry;
}

__global__ void scatter_kernel(const int* __restrict__ ei,
                               int* __restrict__ cur, int* __restrict__ adj) {
    int e = blockIdx.x * blockDim.x + threadIdx.x;
    if (e >= ETOT) return;
    int src, dst;
    if (e < N_EDGES) { src = ei[e]; dst = ei[N_EDGES + e]; }
    else             { src = dst = e - N_EDGES; }
    int pos = atomicAdd(&cur[dst], 1);
    adj[pos] = src;
}

// ---------------- fused GAT attention + aggregation + bias + ELU (warp per node) ----------------
__device__ __forceinline__ float lrelu(float v) { return v > 0.f ? v : 0.2f * v; }
__device__ __forceinline__ float pick4(float4 v, int h) {
    float lo = (h == 0) ? v.x : v.y;
    float hi = (h == 2) ? v.z : v.w;
    return (h < 2) ? lo : hi;
}

__global__ __launch_bounds__(256) void gat_fused_kernel(
    const int* __restrict__ off, const int* __restrict__ adj,
    const float* __restrict__ proj, const float* __restrict__ als,
    const float* __restrict__ ald, const float* __restrict__ bias,
    float* __restrict__ hout) {
    __shared__ float sE[8][CAP][4];
    __shared__ int   sS[8][CAP];
    int w = threadIdx.x >> 5, lane = threadIdx.x & 31;
    int n = blockIdx.x * 8 + w;
    if (n >= N_NODES) return;
    int e0 = off[n];
    int deg = off[n + 1] - e0;
    float4 aldn = ((const float4*)ald)[n];

    // pass 1: logits + cache + per-head max
    float4 mx = make_float4(-INFINITY, -INFINITY, -INFINITY, -INFINITY);
    for (int j = lane; j < deg; j += 32) {
        int s = adj[e0 + j];
        float4 a = ((const float4*)als)[s];
        float4 e;
        e.x = lrelu(a.x + aldn.x);
        e.y = lrelu(a.y + aldn.y);
        e.z = lrelu(a.z + aldn.z);
        e.w = lrelu(a.w + aldn.w);
        if (j < CAP) { sS[w][j] = s; *(float4*)sE[w][j] = e; }
        mx.x = fmaxf(mx.x, e.x); mx.y = fmaxf(mx.y, e.y);
        mx.z = fmaxf(mx.z, e.z); mx.w = fmaxf(mx.w, e.w);
    }
#pragma unroll
    for (int o = 16; o; o >>= 1) {
        mx.x = fmaxf(mx.x, __shfl_xor_sync(0xFFFFFFFFu, mx.x, o));
        mx.y = fmaxf(mx.y, __shfl_xor_sync(0xFFFFFFFFu, mx.y, o));
        mx.z = fmaxf(mx.z, __shfl_xor_sync(0xFFFFFFFFu, mx.z, o));
        mx.w = fmaxf(mx.w, __shfl_xor_sync(0xFFFFFFFFu, mx.w, o));
    }

    // pass 2: exp + sum (overwrite cache with exp values)
    float4 sum = make_float4(0.f, 0.f, 0.f, 0.f);
    for (int j = lane; j < deg; j += 32) {
        float4 e;
        if (j < CAP) e = *(float4*)sE[w][j];
        else {
            int s = adj[e0 + j];
            float4 a = ((const float4*)als)[s];
            e.x = lrelu(a.x + aldn.x); e.y = lrelu(a.y + aldn.y);
            e.z = lrelu(a.z + aldn.z); e.w = lrelu(a.w + aldn.w);
        }
        float4 g;
        g.x = expf(e.x - mx.x); g.y = expf(e.y - mx.y);
        g.z = expf(e.z - mx.z); g.w = expf(e.w - mx.w);
        if (j < CAP) *(float4*)sE[w][j] = g;
        sum.x += g.x; sum.y += g.y; sum.z += g.z; sum.w += g.w;
    }
#pragma unroll
    for (int o = 16; o; o >>= 1) {
        sum.x += __shfl_xor_sync(0xFFFFFFFFu, sum.x, o);
        sum.y += __shfl_xor_sync(0xFFFFFFFFu, sum.y, o);
        sum.z += __shfl_xor_sync(0xFFFFFFFFu, sum.z, o);
        sum.w += __shfl_xor_sync(0xFFFFFFFFu, sum.w, o);
    }
    int hsel = lane >> 3;                 // which head this lane's features belong to
    float invh = 1.0f / (pick4(sum, hsel) + 1e-16f);
    float mxh  = pick4(mx, hsel);

    // pass 3: weighted aggregation (whole warp per edge; 8 features per lane)
    float acc0 = 0.f, acc1 = 0.f, acc2 = 0.f, acc3 = 0.f;
    float acc4 = 0.f, acc5 = 0.f, acc6 = 0.f, acc7 = 0.f;
    for (int j = 0; j < deg; j++) {
        int s; float g;
        if (j < CAP) { s = sS[w][j]; g = sE[w][j][hsel]; }
        else {
            s = adj[e0 + j];
            float4 a = ((const float4*)als)[s];
            float eh = lrelu(pick4(a, hsel) + pick4(aldn, hsel));
            g = expf(eh - mxh);
        }
        float alpha = g * invh;
        const float4* pr = (const float4*)(proj + (size_t)s * DDIM);
        float4 v0 = pr[lane * 2];
        float4 v1 = pr[lane * 2 + 1];
        acc0 += alpha * v0.x; acc1 += alpha * v0.y;
        acc2 += alpha * v0.z; acc3 += alpha * v0.w;
        acc4 += alpha * v1.x; acc5 += alpha * v1.y;
        acc6 += alpha * v1.z; acc7 += alpha * v1.w;
    }

    // bias + ELU + write
    const float4* b4 = (const float4*)bias;
    float4 b0 = b4[lane * 2], b1 = b4[lane * 2 + 1];
    float4 o0, o1;
    o0.x = acc0 + b0.x; o0.x = o0.x > 0.f ? o0.x : expm1f(o0.x);
    o0.y = acc1 + b0.y; o0.y = o0.y > 0.f ? o0.y : expm1f(o0.y);
    o0.z = acc2 + b0.z; o0.z = o0.z > 0.f ? o0.z : expm1f(o0.z);
    o0.w = acc3 + b0.w; o0.w = o0.w > 0.f ? o0.w : expm1f(o0.w);
    o1.x = acc4 + b1.x; o1.x = o1.x > 0.f ? o1.x : expm1f(o1.x);
    o1.y = acc5 + b1.y; o1.y = o1.y > 0.f ? o1.y : expm1f(o1.y);
    o1.z = acc6 + b1.z; o1.z = o1.z > 0.f ? o1.z : expm1f(o1.z);
    o1.w = acc7 + b1.w; o1.w = o1.w > 0.f ? o1.w : expm1f(o1.w);
    float4* out4 = (float4*)(hout + (size_t)n * DDIM);
    out4[lane * 2]     = o0;
    out4[lane * 2 + 1] = o1;
}

// ---------------- mean pool over sorted batch ----------------
#define PCHUNK 256
__global__ void pool_kernel(const float* __restrict__ h, const int* __restrict__ batch,
                            float* __restrict__ sums, float* __restrict__ cnt) {
    __shared__ int sb[PCHUNK];
    int n0 = blockIdx.x * PCHUNK;
    int n1 = min(N_NODES, n0 + PCHUNK);
    int cnt_local = n1 - n0;
    for (int i = threadIdx.x; i < cnt_local; i += blockDim.x) sb[i] = batch[n0 + i];
    __syncthreads();
    int t = threadIdx.x;     // feature index, 256 threads
    float acc = 0.0f;
    int gp = sb[0];
    for (int i = 0; i < cnt_local; i++) {
        int g = sb[i];
        if (g != gp) { atomicAdd(&sums[gp * DDIM + t], acc); acc = 0.0f; gp = g; }
        acc += h[(size_t)(n0 + i) * DDIM + t];
    }
    atomicAdd(&sums[gp * DDIM + t], acc);
    if (t == 0) {
        float c = 0.0f; gp = sb[0];
        for (int i = 0; i < cnt_local; i++) {
            int g = sb[i];
            if (g != gp) { atomicAdd(&cnt[gp], c); c = 0.0f; gp = g; }
            c += 1.0f;
        }
        atomicAdd(&cnt[gp], c);
    }
}

// ---------------- decoder: mean -> Linear -> LN -> ReLU -> Linear ----------------
__global__ void decoder_kernel(const float* __restrict__ sums, const float* __restrict__ cnt,
                               const float* __restrict__ w1, const float* __restrict__ b1,
                               const float* __restrict__ gam, const float* __restrict__ bet,
                               const float* __restrict__ w2, const float* __restrict__ b2,
                               float* __restrict__ out) {
    __shared__ float p[DDIM];
    __shared__ float y[64];
    int t = threadIdx.x;     // 64 threads
    for (int gr = 0; gr < NGRP; gr++) {
        float invc = 1.0f / fmaxf(cnt[gr], 1.0f);
        for (int i = t; i < DDIM; i += 64) p[i] = sums[gr * DDIM + i] * invc;
        __syncthreads();
        float acc = b1[t];
        for (int k = 0; k < DDIM; k++) acc += p[k] * w1[k * 64 + t];
        y[t] = acc;
        __syncthreads();
        float m = 0.0f;
        for (int k = 0; k < 64; k++) m += y[k];
        m *= (1.0f / 64.0f);
        float v = 0.0f;
        for (int k = 0; k < 64; k++) { float d = y[k] - m; v += d * d; }
        v *= (1.0f / 64.0f);
        float z = fmaxf(0.0f, gam[t] * (acc - m) * rsqrtf(v + EPS_LN) + bet[t]);
        __syncthreads();
        y[t] = z;
        __syncthreads();
        if (t < OUTF) {
            float o = b2[t];
            for (int k = 0; k < 64; k++) o += y[k] * w2[k * OUTF + t];
            out[gr * OUTF + t] = o;
        }
        __syncthreads();
    }
}

// ---------------- orchestration ----------------
extern "C" void kernel_launch(void* const* d_in, const int* in_sizes, int n_in,
                              void* d_out, int out_size) {
    const float* x      = (const float*)d_in[0];
    const int*   ei     = (const int*)d_in[1];
    const int*   batch  = (const int*)d_in[2];
    const float* enc_w1 = (const float*)d_in[3];
    const float* enc_b1 = (const float*)d_in[4];
    const float* enc_g  = (const float*)d_in[5];
    const float* enc_be = (const float*)d_in[6];
    const float* enc_w2 = (const float*)d_in[7];
    const float* enc_b2 = (const float*)d_in[8];
    const float* convW[3]  = { (const float*)d_in[9],  (const float*)d_in[13], (const float*)d_in[17] };
    const float* convAS[3] = { (const float*)d_in[10], (const float*)d_in[14], (const float*)d_in[18] };
    const float* convAD[3] = { (const float*)d_in[11], (const float*)d_in[15], (const float*)d_in[19] };
    const float* convB[3]  = { (const float*)d_in[12], (const float*)d_in[16], (const float*)d_in[20] };
    const float* dec_w1 = (const float*)d_in[21];
    const float* dec_b1 = (const float*)d_in[22];
    const float* dec_g  = (const float*)d_in[23];
    const float* dec_be = (const float*)d_in[24];
    const float* dec_w2 = (const float*)d_in[25];
    const float* dec_b2 = (const float*)d_in[26];

    float *bufA, *bufB, *proj, *als, *ald, *sums, *cnt;
    int *deg, *off, *cur, *adj;
    cudaGetSymbolAddress((void**)&bufA, g_bufA);
    cudaGetSymbolAddress((void**)&bufB, g_bufB);
    cudaGetSymbolAddress((void**)&proj, g_proj);
    cudaGetSymbolAddress((void**)&als,  g_als);
    cudaGetSymbolAddress((void**)&ald,  g_ald);
    cudaGetSymbolAddress((void**)&deg,  g_deg);
    cudaGetSymbolAddress((void**)&off,  g_off);
    cudaGetSymbolAddress((void**)&cur,  g_cur);
    cudaGetSymbolAddress((void**)&adj,  g_adj);
    cudaGetSymbolAddress((void**)&sums, g_sums);
    cudaGetSymbolAddress((void**)&cnt,  g_cnt);

    // CSR build (topology fixed across the 3 layers)
    cudaMemsetAsync(deg, 0, N_NODES * sizeof(int));
    hist_kernel<<<(ETOT + 255) / 256, 256>>>(ei, deg);
    scan_kernel<<<1, SCAN_T>>>(deg, off, cur);
    scatter_kernel<<<(ETOT + 255) / 256, 256>>>(ei, cur, adj);

    // encoder -> bufA as [N,64]
    encoder_kernel<<<N_NODES, 64>>>(x, enc_w1, enc_b1, enc_g, enc_be, enc_w2, enc_b2, bufA);

    float* hin = bufA;
    float* hout = bufB;
    int Fin = HID;
    for (int L = 0; L < 3; L++) {
        dim3 ggrid(DDIM / GBN, (N_NODES + GBM - 1) / GBM);
        sgemm128_kernel<<<ggrid, 256>>>(hin, convW[L], proj, N_NODES, Fin);
        attcoef_kernel<<<(N_NODES * 32 + 255) / 256, 256>>>(proj, convAS[L], convAD[L], als, ald);
        gat_fused_kernel<<<(N_NODES + 7) / 8, 256>>>(off, adj, proj, als, ald, convB[L], hout);
        float* tmp = hin; hin = hout; hout = tmp;
        Fin = DDIM;
    }

    cudaMemsetAsync(sums, 0, NGRP * DDIM * sizeof(float));
    cudaMemsetAsync(cnt, 0, NGRP * sizeof(float));
    pool_kernel<<<(N_NODES + PCHUNK - 1) / PCHUNK, 256>>>(hin, batch, sums, cnt);
    decoder_kernel<<<1, 64>>>(sums, cnt, dec_w1, dec_b1, dec_g, dec_be, dec_w2, dec_b2,
                              (float*)d_out);
}

// round 4
// speedup vs baseline: 1.9821x; 1.4251x over previous
#include <cuda_runtime.h>
#include <cuda_bf16.h>
#include <math.h>
#include <stdint.h>

#define N_NODES 50000
#define N_EDGES 800000
#define ETOT    850000   // edges + self loops
#define HID     64
#define HEADS   4
#define DDIM    256      // HID*HEADS
#define OUTF    40
#define NGRP    8
#define EPS_LN  1e-5f
#define CAP     96

// ---------------- scratch (device globals; no dynamic alloc allowed) ----------------
__device__ float g_bufA[(size_t)N_NODES * DDIM];
__device__ float g_bufB[(size_t)N_NODES * DDIM];
__device__ float g_proj[(size_t)N_NODES * DDIM];
__device__ float g_als[N_NODES * HEADS];
__device__ float g_ald[N_NODES * HEADS];
__device__ int   g_deg[N_NODES];
__device__ int   g_off[N_NODES + 1];
__device__ int   g_cur[N_NODES];
__device__ int   g_adj[ETOT];
__device__ float g_sums[NGRP * DDIM];
__device__ float g_cnt[NGRP];
__device__ __nv_bfloat16 g_wthi[DDIM * DDIM];   // W^T hi, [N=256][K]
__device__ __nv_bfloat16 g_wtlo[DDIM * DDIM];   // W^T lo
#define NB_CSR ((N_NODES + 255) / 256)
__device__ int g_bsum[NB_CSR];
__device__ int g_boff[NB_CSR];

// ---------------- W prep: transpose + bf16 hi/lo split ----------------
__global__ void prep_wt_kernel(const float* __restrict__ W,
                               __nv_bfloat16* __restrict__ hi,
                               __nv_bfloat16* __restrict__ lo, int K) {
    int n = blockIdx.x;                    // 0..255
    for (int k = threadIdx.x; k < K; k += blockDim.x) {
        float v = W[(size_t)k * DDIM + n];
        __nv_bfloat16 h = __float2bfloat16(v);
        float r = v - __bfloat162float(h);
        hi[(size_t)n * K + k] = h;
        lo[(size_t)n * K + k] = __float2bfloat16(r);
    }
}

// ---------------- bf16x3 HMMA GEMM: C[M,256] = A[M,K] @ W[K,256] ----------------
// Block: 128 (M) x 128 (N); 8 warps as 4(M) x 2(N); warp tile 32 x 64.
// B provided pre-transposed/split as Wt[n][k] bf16 hi/lo.
#define KCH 32
#define LDK 36          // padded smem row length (bf16 elems)

__device__ __forceinline__ void mma_bf16(float* c, uint32_t a0, uint32_t a1,
                                         uint32_t a2, uint32_t a3,
                                         uint32_t b0, uint32_t b1) {
    asm volatile(
        "mma.sync.aligned.m16n8k16.row.col.f32.bf16.bf16.f32 "
        "{%0,%1,%2,%3}, {%4,%5,%6,%7}, {%8,%9}, {%0,%1,%2,%3};"
        : "+f"(c[0]), "+f"(c[1]), "+f"(c[2]), "+f"(c[3])
        : "r"(a0), "r"(a1), "r"(a2), "r"(a3), "r"(b0), "r"(b1));
}

__global__ __launch_bounds__(256) void gemm_mma_kernel(
    const float* __restrict__ A,
    const __nv_bfloat16* __restrict__ BH, const __nv_bfloat16* __restrict__ BL,
    float* __restrict__ C, int M, int K) {
    __shared__ __align__(16) __nv_bfloat16 sAh[128][LDK];
    __shared__ __align__(16) __nv_bfloat16 sAl[128][LDK];
    __shared__ __align__(16) __nv_bfloat16 sBh[128][LDK];
    __shared__ __align__(16) __nv_bfloat16 sBl[128][LDK];

    int tid = threadIdx.x;
    int warp = tid >> 5, lane = tid & 31;
    int g = lane >> 2, tg = lane & 3;
    int warpM = warp & 3, warpN = warp >> 2;   // 4 x 2
    int bm0 = blockIdx.y * 128;
    int bn0 = blockIdx.x * 128;

    float acc[2][8][4];
#pragma unroll
    for (int i = 0; i < 2; i++)
#pragma unroll
        for (int j = 0; j < 8; j++)
#pragma unroll
            for (int q = 0; q < 4; q++) acc[i][j][q] = 0.f;

    int rowLoc = tid >> 1;
    int kq = (tid & 1) * 16;
    int grow = bm0 + rowLoc;
    bool rok = grow < M;

    for (int k0 = 0; k0 < K; k0 += KCH) {
        // ---- A tile: fp32 -> bf16 hi/lo ----
        {
            const float4* ap = (const float4*)(A + (size_t)grow * K + k0 + kq);
#pragma unroll
            for (int q = 0; q < 4; q++) {
                float4 v = rok ? ap[q] : make_float4(0.f, 0.f, 0.f, 0.f);
                __nv_bfloat16 h0 = __float2bfloat16(v.x), h1 = __float2bfloat16(v.y);
                __nv_bfloat16 h2 = __float2bfloat16(v.z), h3 = __float2bfloat16(v.w);
                __nv_bfloat16 l0 = __float2bfloat16(v.x - __bfloat162float(h0));
                __nv_bfloat16 l1 = __float2bfloat16(v.y - __bfloat162float(h1));
                __nv_bfloat16 l2 = __float2bfloat16(v.z - __bfloat162float(h2));
                __nv_bfloat16 l3 = __float2bfloat16(v.w - __bfloat162float(h3));
                uint32_t hA = (uint32_t)__bfloat16_as_ushort(h0) | ((uint32_t)__bfloat16_as_ushort(h1) << 16);
                uint32_t hB = (uint32_t)__bfloat16_as_ushort(h2) | ((uint32_t)__bfloat16_as_ushort(h3) << 16);
                uint32_t lA = (uint32_t)__bfloat16_as_ushort(l0) | ((uint32_t)__bfloat16_as_ushort(l1) << 16);
                uint32_t lB = (uint32_t)__bfloat16_as_ushort(l2) | ((uint32_t)__bfloat16_as_ushort(l3) << 16);
                *(uint32_t*)&sAh[rowLoc][kq + q * 4]     = hA;
                *(uint32_t*)&sAh[rowLoc][kq + q * 4 + 2] = hB;
                *(uint32_t*)&sAl[rowLoc][kq + q * 4]     = lA;
                *(uint32_t*)&sAl[rowLoc][kq + q * 4 + 2] = lB;
            }
        }
        // ---- B tile: pre-split bf16 [n][k] ----
        {
            const uint4* bh = (const uint4*)(BH + (size_t)(bn0 + rowLoc) * K + k0 + kq);
            const uint4* bl = (const uint4*)(BL + (size_t)(bn0 + rowLoc) * K + k0 + kq);
            uint4 vh0 = bh[0], vh1 = bh[1];
            uint4 vl0 = bl[0], vl1 = bl[1];
            uint32_t* dh = (uint32_t*)&sBh[rowLoc][kq];
            uint32_t* dl = (uint32_t*)&sBl[rowLoc][kq];
            dh[0] = vh0.x; dh[1] = vh0.y; dh[2] = vh0.z; dh[3] = vh0.w;
            dh[4] = vh1.x; dh[5] = vh1.y; dh[6] = vh1.z; dh[7] = vh1.w;
            dl[0] = vl0.x; dl[1] = vl0.y; dl[2] = vl0.z; dl[3] = vl0.w;
            dl[4] = vl1.x; dl[5] = vl1.y; dl[6] = vl1.z; dl[7] = vl1.w;
        }
        __syncthreads();

#pragma unroll
        for (int ks = 0; ks < 2; ks++) {
            int kb = ks * 16 + tg * 2;
            uint32_t ah[2][4], al[2][4];
#pragma unroll
            for (int mt = 0; mt < 2; mt++) {
                int r0 = warpM * 32 + mt * 16 + g;
                ah[mt][0] = *(const uint32_t*)&sAh[r0][kb];
                ah[mt][1] = *(const uint32_t*)&sAh[r0 + 8][kb];
                ah[mt][2] = *(const uint32_t*)&sAh[r0][kb + 8];
                ah[mt][3] = *(const uint32_t*)&sAh[r0 + 8][kb + 8];
                al[mt][0] = *(const uint32_t*)&sAl[r0][kb];
                al[mt][1] = *(const uint32_t*)&sAl[r0 + 8][kb];
                al[mt][2] = *(const uint32_t*)&sAl[r0][kb + 8];
                al[mt][3] = *(const uint32_t*)&sAl[r0 + 8][kb + 8];
            }
#pragma unroll
            for (int nt = 0; nt < 8; nt++) {
                int nc = warpN * 64 + nt * 8 + g;
                uint32_t bh0 = *(const uint32_t*)&sBh[nc][kb];
                uint32_t bh1 = *(const uint32_t*)&sBh[nc][kb + 8];
                uint32_t bl0 = *(const uint32_t*)&sBl[nc][kb];
                uint32_t bl1 = *(const uint32_t*)&sBl[nc][kb + 8];
#pragma unroll
                for (int mt = 0; mt < 2; mt++) {
                    mma_bf16(acc[mt][nt], ah[mt][0], ah[mt][1], ah[mt][2], ah[mt][3], bh0, bh1);
                    mma_bf16(acc[mt][nt], ah[mt][0], ah[mt][1], ah[mt][2], ah[mt][3], bl0, bl1);
                    mma_bf16(acc[mt][nt], al[mt][0], al[mt][1], al[mt][2], al[mt][3], bh0, bh1);
                }
            }
        }
        __syncthreads();
    }

    // ---- epilogue ----
#pragma unroll
    for (int mt = 0; mt < 2; mt++) {
        int r0 = bm0 + warpM * 32 + mt * 16 + g;
#pragma unroll
        for (int nt = 0; nt < 8; nt++) {
            int col = bn0 + warpN * 64 + nt * 8 + tg * 2;
            if (r0 < M)
                *(float2*)(C + (size_t)r0 * DDIM + col) = make_float2(acc[mt][nt][0], acc[mt][nt][1]);
            if (r0 + 8 < M)
                *(float2*)(C + (size_t)(r0 + 8) * DDIM + col) = make_float2(acc[mt][nt][2], acc[mt][nt][3]);
        }
    }
}

// ---------------- encoder: 64-node tiles, weights cached in smem ----------------
#define ENC_SMEM ((8448 + 8192 + 4352) * 4)
__global__ __launch_bounds__(256) void encoder_kernel(
    const float* __restrict__ x,
    const float* __restrict__ w1, const float* __restrict__ b1,
    const float* __restrict__ gam, const float* __restrict__ bet,
    const float* __restrict__ w2, const float* __restrict__ b2,
    float* __restrict__ h0) {
    extern __shared__ float sm[];
    float* xs = sm;             // [64][132]
    float* ws = sm + 8448;      // [128][64] then [64][64]
    float* ys = sm + 16640;     // [64][68]
    int t = threadIdx.x;
    int n0 = blockIdx.x * 64;
    for (int i = t; i < 64 * 128; i += 256) {
        int nd = i >> 7, k = i & 127;
        int gn = n0 + nd;
        xs[nd * 132 + k] = (gn < N_NODES) ? x[(size_t)gn * 128 + k] : 0.f;
    }
    for (int i = t; i < 128 * 64; i += 256) ws[i] = w1[i];
    __syncthreads();
    int tx = t & 15, ty = t >> 4;
    float acc[4][4] = {};
#pragma unroll 4
    for (int k = 0; k < 128; k++) {
        float4 b4 = *(const float4*)&ws[k * 64 + tx * 4];
        float a0 = xs[(ty * 4 + 0) * 132 + k];
        float a1 = xs[(ty * 4 + 1) * 132 + k];
        float a2 = xs[(ty * 4 + 2) * 132 + k];
        float a3 = xs[(ty * 4 + 3) * 132 + k];
        acc[0][0] += a0 * b4.x; acc[0][1] += a0 * b4.y; acc[0][2] += a0 * b4.z; acc[0][3] += a0 * b4.w;
        acc[1][0] += a1 * b4.x; acc[1][1] += a1 * b4.y; acc[1][2] += a1 * b4.z; acc[1][3] += a1 * b4.w;
        acc[2][0] += a2 * b4.x; acc[2][1] += a2 * b4.y; acc[2][2] += a2 * b4.z; acc[2][3] += a2 * b4.w;
        acc[3][0] += a3 * b4.x; acc[3][1] += a3 * b4.y; acc[3][2] += a3 * b4.z; acc[3][3] += a3 * b4.w;
    }
    float4 b1v = *(const float4*)&b1[tx * 4];
#pragma unroll
    for (int i = 0; i < 4; i++)
        *(float4*)&ys[(ty * 4 + i) * 68 + tx * 4] = make_float4(
            acc[i][0] + b1v.x, acc[i][1] + b1v.y, acc[i][2] + b1v.z, acc[i][3] + b1v.w);
    __syncthreads();
    {
        int nd = t >> 2, q = t & 3;
        float s1 = 0.f, s2 = 0.f;
#pragma unroll
        for (int j = 0; j < 16; j++) {
            float v = ys[nd * 68 + q * 16 + j];
            s1 += v; s2 += v * v;
        }
        s1 += __shfl_xor_sync(0xFFFFFFFFu, s1, 1); s2 += __shfl_xor_sync(0xFFFFFFFFu, s2, 1);
        s1 += __shfl_xor_sync(0xFFFFFFFFu, s1, 2); s2 += __shfl_xor_sync(0xFFFFFFFFu, s2, 2);
        float m = s1 * (1.f / 64.f);
        float var = s2 * (1.f / 64.f) - m * m;
        float inv = rsqrtf(var + EPS_LN);
#pragma unroll
        for (int j = 0; j < 16; j++) {
            int col = q * 16 + j;
            float v = ys[nd * 68 + col];
            float z = gam[col] * (v - m) * inv + bet[col];
            ys[nd * 68 + col] = fmaxf(z, 0.f);
        }
    }
    __syncthreads();
    for (int i = t; i < 64 * 64; i += 256) ws[i] = w2[i];
    __syncthreads();
    float acc2[4][4] = {};
#pragma unroll 4
    for (int k = 0; k < 64; k++) {
        float4 b4 = *(const float4*)&ws[k * 64 + tx * 4];
        float a0 = ys[(ty * 4 + 0) * 68 + k];
        float a1 = ys[(ty * 4 + 1) * 68 + k];
        float a2 = ys[(ty * 4 + 2) * 68 + k];
        float a3 = ys[(ty * 4 + 3) * 68 + k];
        acc2[0][0] += a0 * b4.x; acc2[0][1] += a0 * b4.y; acc2[0][2] += a0 * b4.z; acc2[0][3] += a0 * b4.w;
        acc2[1][0] += a1 * b4.x; acc2[1][1] += a1 * b4.y; acc2[1][2] += a1 * b4.z; acc2[1][3] += a1 * b4.w;
        acc2[2][0] += a2 * b4.x; acc2[2][1] += a2 * b4.y; acc2[2][2] += a2 * b4.z; acc2[2][3] += a2 * b4.w;
        acc2[3][0] += a3 * b4.x; acc2[3][1] += a3 * b4.y; acc2[3][2] += a3 * b4.z; acc2[3][3] += a3 * b4.w;
    }
    float4 b2v = *(const float4*)&b2[tx * 4];
#pragma unroll
    for (int i = 0; i < 4; i++) {
        int gn = n0 + ty * 4 + i;
        if (gn < N_NODES)
            *(float4*)&h0[(size_t)gn * 64 + tx * 4] = make_float4(
                acc2[i][0] + b2v.x, acc2[i][1] + b2v.y, acc2[i][2] + b2v.z, acc2[i][3] + b2v.w);
    }
}

// ---------------- attention coefficients: al_s/al_d [N,H] ----------------
__global__ void attcoef_kernel(const float* __restrict__ hp,
                               const float* __restrict__ a_s,
                               const float* __restrict__ a_d,
                               float* __restrict__ als, float* __restrict__ ald) {
    int w = (blockIdx.x * blockDim.x + threadIdx.x) >> 5;
    int lane = threadIdx.x & 31;
    if (w >= N_NODES) return;
    const float* row = hp + (size_t)w * DDIM;
#pragma unroll
    for (int h = 0; h < HEADS; h++) {
        float v1 = row[h * 64 + lane];
        float v2 = row[h * 64 + 32 + lane];
        float ps = v1 * a_s[h * 64 + lane] + v2 * a_s[h * 64 + 32 + lane];
        float pd = v1 * a_d[h * 64 + lane] + v2 * a_d[h * 64 + 32 + lane];
#pragma unroll
        for (int o = 16; o; o >>= 1) {
            ps += __shfl_xor_sync(0xFFFFFFFFu, ps, o);
            pd += __shfl_xor_sync(0xFFFFFFFFu, pd, o);
        }
        if (lane == 0) { als[w * HEADS + h] = ps; ald[w * HEADS + h] = pd; }
    }
}

// ---------------- CSR build (two-level scan) ----------------
__global__ void hist_kernel(const int* __restrict__ ei, int* __restrict__ deg) {
    int e = blockIdx.x * blockDim.x + threadIdx.x;
    if (e >= ETOT) return;
    int dst = (e < N_EDGES) ? ei[N_EDGES + e] : (e - N_EDGES);
    atomicAdd(&deg[dst], 1);
}

__global__ void degsum_kernel(const int* __restrict__ deg, int* __restrict__ bsum) {
    __shared__ int red[256];
    int b = blockIdx.x, t = threadIdx.x;
    int i = b * 256 + t;
    red[t] = (i < N_NODES) ? deg[i] : 0;
    __syncthreads();
    for (int o = 128; o; o >>= 1) { if (t < o) red[t] += red[t + o]; __syncthreads(); }
    if (t == 0) bsum[b] = red[0];
}

__global__ void scanb_kernel(const int* __restrict__ bsum, int* __restrict__ boff) {
    __shared__ int s[256];
    int t = threadIdx.x;
    int v0 = (t < NB_CSR) ? bsum[t] : 0;
    s[t] = v0;
    __syncthreads();
    for (int o = 1; o < 256; o <<= 1) {
        int v = (t >= o) ? s[t - o] : 0;
        __syncthreads();
        s[t] += v;
        __syncthreads();
    }
    if (t < NB_CSR) boff[t] = s[t] - v0;
}

__global__ void offsets_kernel(const int* __restrict__ deg, const int* __restrict__ boff,
                               int* __restrict__ off, int* __restrict__ cur) {
    __shared__ int s[256];
    int b = blockIdx.x, t = threadIdx.x;
    int i = b * 256 + t;
    int d = (i < N_NODES) ? deg[i] : 0;
    s[t] = d;
    __syncthreads();
    for (int o = 1; o < 256; o <<= 1) {
        int v = (t >= o) ? s[t - o] : 0;
        __syncthreads();
        s[t] += v;
        __syncthreads();
    }
    int excl = boff[b] + s[t] - d;
    if (i < N_NODES) { off[i] = excl; cur[i] = excl; }
    if (b == 0 && t == 0) off[N_NODES] = ETOT;
}

__global__ void scatter_kernel(const int* __restrict__ ei,
                               int* __restrict__ cur, int* __restrict__ adj) {
    int e = blockIdx.x * blockDim.x + threadIdx.x;
    if (e >= ETOT) return;
    int src, dst;
    if (e < N_EDGES) { src = ei[e]; dst = ei[N_EDGES + e]; }
    else             { src = dst = e - N_EDGES; }
    int pos = atomicAdd(&cur[dst], 1);
    adj[pos] = src;
}

// ---------------- fused GAT attention + aggregation + bias + ELU (warp per node) ----------------
__device__ __forceinline__ float lrelu(float v) { return v > 0.f ? v : 0.2f * v; }
__device__ __forceinline__ float pick4(float4 v, int h) {
    float lo = (h == 0) ? v.x : v.y;
    float hi = (h == 2) ? v.z : v.w;
    return (h < 2) ? lo : hi;
}

__global__ __launch_bounds__(256) void gat_fused_kernel(
    const int* __restrict__ off, const int* __restrict__ adj,
    const float* __restrict__ proj, const float* __restrict__ als,
    const float* __restrict__ ald, const float* __restrict__ bias,
    float* __restrict__ hout) {
    __shared__ float sE[8][CAP][4];
    __shared__ int   sS[8][CAP];
    int w = threadIdx.x >> 5, lane = threadIdx.x & 31;
    int n = blockIdx.x * 8 + w;
    if (n >= N_NODES) return;
    int e0 = off[n];
    int deg = off[n + 1] - e0;
    float4 aldn = ((const float4*)ald)[n];

    float4 mx = make_float4(-INFINITY, -INFINITY, -INFINITY, -INFINITY);
    for (int j = lane; j < deg; j += 32) {
        int s = adj[e0 + j];
        float4 a = ((const float4*)als)[s];
        float4 e;
        e.x = lrelu(a.x + aldn.x);
        e.y = lrelu(a.y + aldn.y);
        e.z = lrelu(a.z + aldn.z);
        e.w = lrelu(a.w + aldn.w);
        if (j < CAP) { sS[w][j] = s; *(float4*)sE[w][j] = e; }
        mx.x = fmaxf(mx.x, e.x); mx.y = fmaxf(mx.y, e.y);
        mx.z = fmaxf(mx.z, e.z); mx.w = fmaxf(mx.w, e.w);
    }
#pragma unroll
    for (int o = 16; o; o >>= 1) {
        mx.x = fmaxf(mx.x, __shfl_xor_sync(0xFFFFFFFFu, mx.x, o));
        mx.y = fmaxf(mx.y, __shfl_xor_sync(0xFFFFFFFFu, mx.y, o));
        mx.z = fmaxf(mx.z, __shfl_xor_sync(0xFFFFFFFFu, mx.z, o));
        mx.w = fmaxf(mx.w, __shfl_xor_sync(0xFFFFFFFFu, mx.w, o));
    }

    float4 sum = make_float4(0.f, 0.f, 0.f, 0.f);
    for (int j = lane; j < deg; j += 32) {
        float4 e;
        if (j < CAP) e = *(float4*)sE[w][j];
        else {
            int s = adj[e0 + j];
            float4 a = ((const float4*)als)[s];
            e.x = lrelu(a.x + aldn.x); e.y = lrelu(a.y + aldn.y);
            e.z = lrelu(a.z + aldn.z); e.w = lrelu(a.w + aldn.w);
        }
        float4 g;
        g.x = expf(e.x - mx.x); g.y = expf(e.y - mx.y);
        g.z = expf(e.z - mx.z); g.w = expf(e.w - mx.w);
        if (j < CAP) *(float4*)sE[w][j] = g;
        sum.x += g.x; sum.y += g.y; sum.z += g.z; sum.w += g.w;
    }
#pragma unroll
    for (int o = 16; o; o >>= 1) {
        sum.x += __shfl_xor_sync(0xFFFFFFFFu, sum.x, o);
        sum.y += __shfl_xor_sync(0xFFFFFFFFu, sum.y, o);
        sum.z += __shfl_xor_sync(0xFFFFFFFFu, sum.z, o);
        sum.w += __shfl_xor_sync(0xFFFFFFFFu, sum.w, o);
    }
    int hsel = lane >> 3;
    float invh = 1.0f / (pick4(sum, hsel) + 1e-16f);
    float mxh  = pick4(mx, hsel);

    float acc0 = 0.f, acc1 = 0.f, acc2 = 0.f, acc3 = 0.f;
    float acc4 = 0.f, acc5 = 0.f, acc6 = 0.f, acc7 = 0.f;
    for (int j = 0; j < deg; j++) {
        int s; float g;
        if (j < CAP) { s = sS[w][j]; g = sE[w][j][hsel]; }
        else {
            s = adj[e0 + j];
            float4 a = ((const float4*)als)[s];
            float eh = lrelu(pick4(a, hsel) + pick4(aldn, hsel));
            g = expf(eh - mxh);
        }
        float alpha = g * invh;
        const float4* pr = (const float4*)(proj + (size_t)s * DDIM);
        float4 v0 = pr[lane * 2];
        float4 v1 = pr[lane * 2 + 1];
        acc0 += alpha * v0.x; acc1 += alpha * v0.y;
        acc2 += alpha * v0.z; acc3 += alpha * v0.w;
        acc4 += alpha * v1.x; acc5 += alpha * v1.y;
        acc6 += alpha * v1.z; acc7 += alpha * v1.w;
    }

    const float4* b4 = (const float4*)bias;
    float4 b0 = b4[lane * 2], b1 = b4[lane * 2 + 1];
    float4 o0, o1;
    o0.x = acc0 + b0.x; o0.x = o0.x > 0.f ? o0.x : expm1f(o0.x);
    o0.y = acc1 + b0.y; o0.y = o0.y > 0.f ? o0.y : expm1f(o0.y);
    o0.z = acc2 + b0.z; o0.z = o0.z > 0.f ? o0.z : expm1f(o0.z);
    o0.w = acc3 + b0.w; o0.w = o0.w > 0.f ? o0.w : expm1f(o0.w);
    o1.x = acc4 + b1.x; o1.x = o1.x > 0.f ? o1.x : expm1f(o1.x);
    o1.y = acc5 + b1.y; o1.y = o1.y > 0.f ? o1.y : expm1f(o1.y);
    o1.z = acc6 + b1.z; o1.z = o1.z > 0.f ? o1.z : expm1f(o1.z);
    o1.w = acc7 + b1.w; o1.w = o1.w > 0.f ? o1.w : expm1f(o1.w);
    float4* out4 = (float4*)(hout + (size_t)n * DDIM);
    out4[lane * 2]     = o0;
    out4[lane * 2 + 1] = o1;
}

// ---------------- mean pool over sorted batch ----------------
#define PCHUNK 256
__global__ void pool_kernel(const float* __restrict__ h, const int* __restrict__ batch,
                            float* __restrict__ sums, float* __restrict__ cnt) {
    __shared__ int sb[PCHUNK];
    int n0 = blockIdx.x * PCHUNK;
    int n1 = min(N_NODES, n0 + PCHUNK);
    int cnt_local = n1 - n0;
    for (int i = threadIdx.x; i < cnt_local; i += blockDim.x) sb[i] = batch[n0 + i];
    __syncthreads();
    int t = threadIdx.x;
    float acc = 0.0f;
    int gp = sb[0];
    for (int i = 0; i < cnt_local; i++) {
        int g = sb[i];
        if (g != gp) { atomicAdd(&sums[gp * DDIM + t], acc); acc = 0.0f; gp = g; }
        acc += h[(size_t)(n0 + i) * DDIM + t];
    }
    atomicAdd(&sums[gp * DDIM + t], acc);
    if (t == 0) {
        float c = 0.0f; gp = sb[0];
        for (int i = 0; i < cnt_local; i++) {
            int g = sb[i];
            if (g != gp) { atomicAdd(&cnt[gp], c); c = 0.0f; gp = g; }
            c += 1.0f;
        }
        atomicAdd(&cnt[gp], c);
    }
}

// ---------------- decoder ----------------
__global__ void decoder_kernel(const float* __restrict__ sums, const float* __restrict__ cnt,
                               const float* __restrict__ w1, const float* __restrict__ b1,
                               const float* __restrict__ gam, const float* __restrict__ bet,
                               const float* __restrict__ w2, const float* __restrict__ b2,
                               float* __restrict__ out) {
    __shared__ float p[DDIM];
    __shared__ float y[64];
    int t = threadIdx.x;
    for (int gr = 0; gr < NGRP; gr++) {
        float invc = 1.0f / fmaxf(cnt[gr], 1.0f);
        for (int i = t; i < DDIM; i += 64) p[i] = sums[gr * DDIM + i] * invc;
        __syncthreads();
        float acc = b1[t];
        for (int k = 0; k < DDIM; k++) acc += p[k] * w1[k * 64 + t];
        y[t] = acc;
        __syncthreads();
        float m = 0.0f;
        for (int k = 0; k < 64; k++) m += y[k];
        m *= (1.0f / 64.0f);
        float v = 0.0f;
        for (int k = 0; k < 64; k++) { float d = y[k] - m; v += d * d; }
        v *= (1.0f / 64.0f);
        float z = fmaxf(0.0f, gam[t] * (acc - m) * rsqrtf(v + EPS_LN) + bet[t]);
        __syncthreads();
        y[t] = z;
        __syncthreads();
        if (t < OUTF) {
            float o = b2[t];
            for (int k = 0; k < 64; k++) o += y[k] * w2[k * OUTF + t];
            out[gr * OUTF + t] = o;
        }
        __syncthreads();
    }
}

// ---------------- orchestration ----------------
extern "C" void kernel_launch(void* const* d_in, const int* in_sizes, int n_in,
                              void* d_out, int out_size) {
    const float* x      = (const float*)d_in[0];
    const int*   ei     = (const int*)d_in[1];
    const int*   batch  = (const int*)d_in[2];
    const float* enc_w1 = (const float*)d_in[3];
    const float* enc_b1 = (const float*)d_in[4];
    const float* enc_g  = (const float*)d_in[5];
    const float* enc_be = (const float*)d_in[6];
    const float* enc_w2 = (const float*)d_in[7];
    const float* enc_b2 = (const float*)d_in[8];
    const float* convW[3]  = { (const float*)d_in[9],  (const float*)d_in[13], (const float*)d_in[17] };
    const float* convAS[3] = { (const float*)d_in[10], (const float*)d_in[14], (const float*)d_in[18] };
    const float* convAD[3] = { (const float*)d_in[11], (const float*)d_in[15], (const float*)d_in[19] };
    const float* convB[3]  = { (const float*)d_in[12], (const float*)d_in[16], (const float*)d_in[20] };
    const float* dec_w1 = (const float*)d_in[21];
    const float* dec_b1 = (const float*)d_in[22];
    const float* dec_g  = (const float*)d_in[23];
    const float* dec_be = (const float*)d_in[24];
    const float* dec_w2 = (const float*)d_in[25];
    const float* dec_b2 = (const float*)d_in[26];

    float *bufA, *bufB, *proj, *als, *ald, *sums, *cnt;
    int *deg, *off, *cur, *adj, *bsum, *boff;
    __nv_bfloat16 *wthi, *wtlo;
    cudaGetSymbolAddress((void**)&bufA, g_bufA);
    cudaGetSymbolAddress((void**)&bufB, g_bufB);
    cudaGetSymbolAddress((void**)&proj, g_proj);
    cudaGetSymbolAddress((void**)&als,  g_als);
    cudaGetSymbolAddress((void**)&ald,  g_ald);
    cudaGetSymbolAddress((void**)&deg,  g_deg);
    cudaGetSymbolAddress((void**)&off,  g_off);
    cudaGetSymbolAddress((void**)&cur,  g_cur);
    cudaGetSymbolAddress((void**)&adj,  g_adj);
    cudaGetSymbolAddress((void**)&sums, g_sums);
    cudaGetSymbolAddress((void**)&cnt,  g_cnt);
    cudaGetSymbolAddress((void**)&bsum, g_bsum);
    cudaGetSymbolAddress((void**)&boff, g_boff);
    cudaGetSymbolAddress((void**)&wthi, g_wthi);
    cudaGetSymbolAddress((void**)&wtlo, g_wtlo);

    cudaFuncSetAttribute(encoder_kernel, cudaFuncAttributeMaxDynamicSharedMemorySize, ENC_SMEM);

    // CSR build
    cudaMemsetAsync(deg, 0, N_NODES * sizeof(int));
    hist_kernel<<<(ETOT + 255) / 256, 256>>>(ei, deg);
    degsum_kernel<<<NB_CSR, 256>>>(deg, bsum);
    scanb_kernel<<<1, 256>>>(bsum, boff);
    offsets_kernel<<<NB_CSR, 256>>>(deg, boff, off, cur);
    scatter_kernel<<<(ETOT + 255) / 256, 256>>>(ei, cur, adj);

    // encoder -> bufA [N,64]
    encoder_kernel<<<(N_NODES + 63) / 64, 256, ENC_SMEM>>>(
        x, enc_w1, enc_b1, enc_g, enc_be, enc_w2, enc_b2, bufA);

    float* hin = bufA;
    float* hout = bufB;
    int Fin = HID;
    for (int L = 0; L < 3; L++) {
        prep_wt_kernel<<<DDIM, 256>>>(convW[L], wthi, wtlo, Fin);
        dim3 ggrid(2, (N_NODES + 127) / 128);
        gemm_mma_kernel<<<ggrid, 256>>>(hin, wthi, wtlo, proj, N_NODES, Fin);
        attcoef_kernel<<<(N_NODES * 32 + 255) / 256, 256>>>(proj, convAS[L], convAD[L], als, ald);
        gat_fused_kernel<<<(N_NODES + 7) / 8, 256>>>(off, adj, proj, als, ald, convB[L], hout);
        float* tmp = hin; hin = hout; hout = tmp;
        Fin = DDIM;
    }

    cudaMemsetAsync(sums, 0, NGRP * DDIM * sizeof(float));
    cudaMemsetAsync(cnt, 0, NGRP * sizeof(float));
    pool_kernel<<<(N_NODES + PCHUNK - 1) / PCHUNK, 256>>>(hin, batch, sums, cnt);
    decoder_kernel<<<1, 64>>>(sums, cnt, dec_w1, dec_b1, dec_g, dec_be, dec_w2, dec_b2,
                              (float*)d_out);
}

// round 5
// speedup vs baseline: 2.1008x; 1.0599x over previous
#include <cuda_runtime.h>
#include <cuda_bf16.h>
#include <math.h>
#include <stdint.h>

#define N_NODES 50000
#define N_EDGES 800000
#define ETOT    850000   // edges + self loops
#define HID     64
#define HEADS   4
#define DDIM    256      // HID*HEADS
#define OUTF    40
#define NGRP    8
#define EPS_LN  1e-5f
#define CAP     96

// ---------------- scratch (device globals; no dynamic alloc allowed) ----------------
__device__ float g_bufA[(size_t)N_NODES * DDIM];
__device__ float g_bufB[(size_t)N_NODES * DDIM];
__device__ __nv_bfloat16 g_projb[(size_t)N_NODES * DDIM];
__device__ float g_als[N_NODES * HEADS];
__device__ float g_ald[N_NODES * HEADS];
__device__ int   g_deg[N_NODES];
__device__ int   g_off[N_NODES + 1];
__device__ int   g_cur[N_NODES];
__device__ int   g_adj[ETOT];
__device__ float g_sums[NGRP * DDIM];
__device__ float g_cnt[NGRP];
__device__ __nv_bfloat16 g_wthi[DDIM * DDIM];   // W^T hi, [N=256][K]
__device__ __nv_bfloat16 g_wtlo[DDIM * DDIM];   // W^T lo
#define NB_CSR ((N_NODES + 255) / 256)
__device__ int g_bsum[NB_CSR];
__device__ int g_boff[NB_CSR];

// ---------------- W prep: transpose + bf16 hi/lo split ----------------
__global__ void prep_wt_kernel(const float* __restrict__ W,
                               __nv_bfloat16* __restrict__ hi,
                               __nv_bfloat16* __restrict__ lo, int K) {
    int n = blockIdx.x;                    // 0..255
    for (int k = threadIdx.x; k < K; k += blockDim.x) {
        float v = W[(size_t)k * DDIM + n];
        __nv_bfloat16 h = __float2bfloat16(v);
        float r = v - __bfloat162float(h);
        hi[(size_t)n * K + k] = h;
        lo[(size_t)n * K + k] = __float2bfloat16(r);
    }
}

// ---------------- bf16x3 HMMA GEMM + fused attcoef + bf16 proj output ----------------
// Block: 128 (M) x 128 (N); 8 warps as 4(M) x 2(N); warp tile 32 x 64 (one head).
#define KCH 32
#define LDK 36          // padded smem row length (bf16 elems)

__device__ __forceinline__ void mma_bf16(float* c, uint32_t a0, uint32_t a1,
                                         uint32_t a2, uint32_t a3,
                                         uint32_t b0, uint32_t b1) {
    asm volatile(
        "mma.sync.aligned.m16n8k16.row.col.f32.bf16.bf16.f32 "
        "{%0,%1,%2,%3}, {%4,%5,%6,%7}, {%8,%9}, {%0,%1,%2,%3};"
        : "+f"(c[0]), "+f"(c[1]), "+f"(c[2]), "+f"(c[3])
        : "r"(a0), "r"(a1), "r"(a2), "r"(a3), "r"(b0), "r"(b1));
}

__global__ __launch_bounds__(256) void gemm_mma_kernel(
    const float* __restrict__ A,
    const __nv_bfloat16* __restrict__ BH, const __nv_bfloat16* __restrict__ BL,
    const float* __restrict__ a_s, const float* __restrict__ a_d,
    __nv_bfloat16* __restrict__ Pb,
    float* __restrict__ als, float* __restrict__ ald,
    int M, int K) {
    __shared__ __align__(16) __nv_bfloat16 sAh[128][LDK];
    __shared__ __align__(16) __nv_bfloat16 sAl[128][LDK];
    __shared__ __align__(16) __nv_bfloat16 sBh[128][LDK];
    __shared__ __align__(16) __nv_bfloat16 sBl[128][LDK];

    int tid = threadIdx.x;
    int warp = tid >> 5, lane = tid & 31;
    int g = lane >> 2, tg = lane & 3;
    int warpM = warp & 3, warpN = warp >> 2;   // 4 x 2
    int bm0 = blockIdx.y * 128;
    int bn0 = blockIdx.x * 128;

    float acc[2][8][4];
#pragma unroll
    for (int i = 0; i < 2; i++)
#pragma unroll
        for (int j = 0; j < 8; j++)
#pragma unroll
            for (int q = 0; q < 4; q++) acc[i][j][q] = 0.f;

    int rowLoc = tid >> 1;
    int kq = (tid & 1) * 16;
    int grow = bm0 + rowLoc;
    bool rok = grow < M;

    for (int k0 = 0; k0 < K; k0 += KCH) {
        // ---- A tile: fp32 -> bf16 hi/lo ----
        {
            const float4* ap = (const float4*)(A + (size_t)grow * K + k0 + kq);
#pragma unroll
            for (int q = 0; q < 4; q++) {
                float4 v = rok ? ap[q] : make_float4(0.f, 0.f, 0.f, 0.f);
                __nv_bfloat16 h0 = __float2bfloat16(v.x), h1 = __float2bfloat16(v.y);
                __nv_bfloat16 h2 = __float2bfloat16(v.z), h3 = __float2bfloat16(v.w);
                __nv_bfloat16 l0 = __float2bfloat16(v.x - __bfloat162float(h0));
                __nv_bfloat16 l1 = __float2bfloat16(v.y - __bfloat162float(h1));
                __nv_bfloat16 l2 = __float2bfloat16(v.z - __bfloat162float(h2));
                __nv_bfloat16 l3 = __float2bfloat16(v.w - __bfloat162float(h3));
                uint32_t hA = (uint32_t)__bfloat16_as_ushort(h0) | ((uint32_t)__bfloat16_as_ushort(h1) << 16);
                uint32_t hB = (uint32_t)__bfloat16_as_ushort(h2) | ((uint32_t)__bfloat16_as_ushort(h3) << 16);
                uint32_t lA = (uint32_t)__bfloat16_as_ushort(l0) | ((uint32_t)__bfloat16_as_ushort(l1) << 16);
                uint32_t lB = (uint32_t)__bfloat16_as_ushort(l2) | ((uint32_t)__bfloat16_as_ushort(l3) << 16);
                *(uint32_t*)&sAh[rowLoc][kq + q * 4]     = hA;
                *(uint32_t*)&sAh[rowLoc][kq + q * 4 + 2] = hB;
                *(uint32_t*)&sAl[rowLoc][kq + q * 4]     = lA;
                *(uint32_t*)&sAl[rowLoc][kq + q * 4 + 2] = lB;
            }
        }
        // ---- B tile: pre-split bf16 [n][k] ----
        {
            const uint4* bh = (const uint4*)(BH + (size_t)(bn0 + rowLoc) * K + k0 + kq);
            const uint4* bl = (const uint4*)(BL + (size_t)(bn0 + rowLoc) * K + k0 + kq);
            uint4 vh0 = bh[0], vh1 = bh[1];
            uint4 vl0 = bl[0], vl1 = bl[1];
            uint32_t* dh = (uint32_t*)&sBh[rowLoc][kq];
            uint32_t* dl = (uint32_t*)&sBl[rowLoc][kq];
            dh[0] = vh0.x; dh[1] = vh0.y; dh[2] = vh0.z; dh[3] = vh0.w;
            dh[4] = vh1.x; dh[5] = vh1.y; dh[6] = vh1.z; dh[7] = vh1.w;
            dl[0] = vl0.x; dl[1] = vl0.y; dl[2] = vl0.z; dl[3] = vl0.w;
            dl[4] = vl1.x; dl[5] = vl1.y; dl[6] = vl1.z; dl[7] = vl1.w;
        }
        __syncthreads();

#pragma unroll
        for (int ks = 0; ks < 2; ks++) {
            int kb = ks * 16 + tg * 2;
            uint32_t ah[2][4], al[2][4];
#pragma unroll
            for (int mt = 0; mt < 2; mt++) {
                int r0 = warpM * 32 + mt * 16 + g;
                ah[mt][0] = *(const uint32_t*)&sAh[r0][kb];
                ah[mt][1] = *(const uint32_t*)&sAh[r0 + 8][kb];
                ah[mt][2] = *(const uint32_t*)&sAh[r0][kb + 8];
                ah[mt][3] = *(const uint32_t*)&sAh[r0 + 8][kb + 8];
                al[mt][0] = *(const uint32_t*)&sAl[r0][kb];
                al[mt][1] = *(const uint32_t*)&sAl[r0 + 8][kb];
                al[mt][2] = *(const uint32_t*)&sAl[r0][kb + 8];
                al[mt][3] = *(const uint32_t*)&sAl[r0 + 8][kb + 8];
            }
#pragma unroll
            for (int nt = 0; nt < 8; nt++) {
                int nc = warpN * 64 + nt * 8 + g;
                uint32_t bh0 = *(const uint32_t*)&sBh[nc][kb];
                uint32_t bh1 = *(const uint32_t*)&sBh[nc][kb + 8];
                uint32_t bl0 = *(const uint32_t*)&sBl[nc][kb];
                uint32_t bl1 = *(const uint32_t*)&sBl[nc][kb + 8];
#pragma unroll
                for (int mt = 0; mt < 2; mt++) {
                    mma_bf16(acc[mt][nt], ah[mt][0], ah[mt][1], ah[mt][2], ah[mt][3], bh0, bh1);
                    mma_bf16(acc[mt][nt], ah[mt][0], ah[mt][1], ah[mt][2], ah[mt][3], bl0, bl1);
                    mma_bf16(acc[mt][nt], al[mt][0], al[mt][1], al[mt][2], al[mt][3], bh0, bh1);
                }
            }
        }
        __syncthreads();
    }

    // ---- epilogue: bf16 proj store + fused attention coefficients ----
    // This warp covers exactly one head: columns [bn0+warpN*64, +64)
    int head = (bn0 >> 6) + warpN;
    float asv[16], adv[16];
#pragma unroll
    for (int nt = 0; nt < 8; nt++) {
#pragma unroll
        for (int q = 0; q < 2; q++) {
            int gcol = bn0 + warpN * 64 + nt * 8 + tg * 2 + q;
            asv[nt * 2 + q] = a_s[gcol];
            adv[nt * 2 + q] = a_d[gcol];
        }
    }
#pragma unroll
    for (int mt = 0; mt < 2; mt++) {
        int r0 = bm0 + warpM * 32 + mt * 16 + g;
        float s_lo = 0.f, s_hi = 0.f, d_lo = 0.f, d_hi = 0.f;
#pragma unroll
        for (int nt = 0; nt < 8; nt++) {
            int col = bn0 + warpN * 64 + nt * 8 + tg * 2;
            // bf16 proj store
            __nv_bfloat162 p0 = __floats2bfloat162_rn(acc[mt][nt][0], acc[mt][nt][1]);
            __nv_bfloat162 p1 = __floats2bfloat162_rn(acc[mt][nt][2], acc[mt][nt][3]);
            if (r0 < M)     *(__nv_bfloat162*)(Pb + (size_t)r0 * DDIM + col) = p0;
            if (r0 + 8 < M) *(__nv_bfloat162*)(Pb + (size_t)(r0 + 8) * DDIM + col) = p1;
            // attcoef partials (fp32 accumulators)
            s_lo += acc[mt][nt][0] * asv[nt * 2] + acc[mt][nt][1] * asv[nt * 2 + 1];
            s_hi += acc[mt][nt][2] * asv[nt * 2] + acc[mt][nt][3] * asv[nt * 2 + 1];
            d_lo += acc[mt][nt][0] * adv[nt * 2] + acc[mt][nt][1] * adv[nt * 2 + 1];
            d_hi += acc[mt][nt][2] * adv[nt * 2] + acc[mt][nt][3] * adv[nt * 2 + 1];
        }
        // reduce over quad (tg = lane&3)
#pragma unroll
        for (int o = 1; o < 4; o <<= 1) {
            s_lo += __shfl_xor_sync(0xFFFFFFFFu, s_lo, o);
            s_hi += __shfl_xor_sync(0xFFFFFFFFu, s_hi, o);
            d_lo += __shfl_xor_sync(0xFFFFFFFFu, d_lo, o);
            d_hi += __shfl_xor_sync(0xFFFFFFFFu, d_hi, o);
        }
        if (tg == 0) {
            if (r0 < M)     { als[r0 * HEADS + head] = s_lo; ald[r0 * HEADS + head] = d_lo; }
            if (r0 + 8 < M) { als[(r0 + 8) * HEADS + head] = s_hi; ald[(r0 + 8) * HEADS + head] = d_hi; }
        }
    }
}

// ---------------- encoder: 64-node tiles, weights cached in smem ----------------
#define ENC_SMEM ((8448 + 8192 + 4352) * 4)
__global__ __launch_bounds__(256) void encoder_kernel(
    const float* __restrict__ x,
    const float* __restrict__ w1, const float* __restrict__ b1,
    const float* __restrict__ gam, const float* __restrict__ bet,
    const float* __restrict__ w2, const float* __restrict__ b2,
    float* __restrict__ h0) {
    extern __shared__ float sm[];
    float* xs = sm;             // [64][132]
    float* ws = sm + 8448;      // [128][64] then [64][64]
    float* ys = sm + 16640;     // [64][68]
    int t = threadIdx.x;
    int n0 = blockIdx.x * 64;
    for (int i = t; i < 64 * 128; i += 256) {
        int nd = i >> 7, k = i & 127;
        int gn = n0 + nd;
        xs[nd * 132 + k] = (gn < N_NODES) ? x[(size_t)gn * 128 + k] : 0.f;
    }
    for (int i = t; i < 128 * 64; i += 256) ws[i] = w1[i];
    __syncthreads();
    int tx = t & 15, ty = t >> 4;
    float acc[4][4] = {};
#pragma unroll 4
    for (int k = 0; k < 128; k++) {
        float4 b4 = *(const float4*)&ws[k * 64 + tx * 4];
        float a0 = xs[(ty * 4 + 0) * 132 + k];
        float a1 = xs[(ty * 4 + 1) * 132 + k];
        float a2 = xs[(ty * 4 + 2) * 132 + k];
        float a3 = xs[(ty * 4 + 3) * 132 + k];
        acc[0][0] += a0 * b4.x; acc[0][1] += a0 * b4.y; acc[0][2] += a0 * b4.z; acc[0][3] += a0 * b4.w;
        acc[1][0] += a1 * b4.x; acc[1][1] += a1 * b4.y; acc[1][2] += a1 * b4.z; acc[1][3] += a1 * b4.w;
        acc[2][0] += a2 * b4.x; acc[2][1] += a2 * b4.y; acc[2][2] += a2 * b4.z; acc[2][3] += a2 * b4.w;
        acc[3][0] += a3 * b4.x; acc[3][1] += a3 * b4.y; acc[3][2] += a3 * b4.z; acc[3][3] += a3 * b4.w;
    }
    float4 b1v = *(const float4*)&b1[tx * 4];
#pragma unroll
    for (int i = 0; i < 4; i++)
        *(float4*)&ys[(ty * 4 + i) * 68 + tx * 4] = make_float4(
            acc[i][0] + b1v.x, acc[i][1] + b1v.y, acc[i][2] + b1v.z, acc[i][3] + b1v.w);
    __syncthreads();
    {
        int nd = t >> 2, q = t & 3;
        float s1 = 0.f, s2 = 0.f;
#pragma unroll
        for (int j = 0; j < 16; j++) {
            float v = ys[nd * 68 + q * 16 + j];
            s1 += v; s2 += v * v;
        }
        s1 += __shfl_xor_sync(0xFFFFFFFFu, s1, 1); s2 += __shfl_xor_sync(0xFFFFFFFFu, s2, 1);
        s1 += __shfl_xor_sync(0xFFFFFFFFu, s1, 2); s2 += __shfl_xor_sync(0xFFFFFFFFu, s2, 2);
        float m = s1 * (1.f / 64.f);
        float var = s2 * (1.f / 64.f) - m * m;
        float inv = rsqrtf(var + EPS_LN);
#pragma unroll
        for (int j = 0; j < 16; j++) {
            int col = q * 16 + j;
            float v = ys[nd * 68 + col];
            float z = gam[col] * (v - m) * inv + bet[col];
            ys[nd * 68 + col] = fmaxf(z, 0.f);
        }
    }
    __syncthreads();
    for (int i = t; i < 64 * 64; i += 256) ws[i] = w2[i];
    __syncthreads();
    float acc2[4][4] = {};
#pragma unroll 4
    for (int k = 0; k < 64; k++) {
        float4 b4 = *(const float4*)&ws[k * 64 + tx * 4];
        float a0 = ys[(ty * 4 + 0) * 68 + k];
        float a1 = ys[(ty * 4 + 1) * 68 + k];
        float a2 = ys[(ty * 4 + 2) * 68 + k];
        float a3 = ys[(ty * 4 + 3) * 68 + k];
        acc2[0][0] += a0 * b4.x; acc2[0][1] += a0 * b4.y; acc2[0][2] += a0 * b4.z; acc2[0][3] += a0 * b4.w;
        acc2[1][0] += a1 * b4.x; acc2[1][1] += a1 * b4.y; acc2[1][2] += a1 * b4.z; acc2[1][3] += a1 * b4.w;
        acc2[2][0] += a2 * b4.x; acc2[2][1] += a2 * b4.y; acc2[2][2] += a2 * b4.z; acc2[2][3] += a2 * b4.w;
        acc2[3][0] += a3 * b4.x; acc2[3][1] += a3 * b4.y; acc2[3][2] += a3 * b4.z; acc2[3][3] += a3 * b4.w;
    }
    float4 b2v = *(const float4*)&b2[tx * 4];
#pragma unroll
    for (int i = 0; i < 4; i++) {
        int gn = n0 + ty * 4 + i;
        if (gn < N_NODES)
            *(float4*)&h0[(size_t)gn * 64 + tx * 4] = make_float4(
                acc2[i][0] + b2v.x, acc2[i][1] + b2v.y, acc2[i][2] + b2v.z, acc2[i][3] + b2v.w);
    }
}

// ---------------- CSR build (two-level scan) ----------------
__global__ void hist_kernel(const int* __restrict__ ei, int* __restrict__ deg) {
    int e = blockIdx.x * blockDim.x + threadIdx.x;
    if (e >= ETOT) return;
    int dst = (e < N_EDGES) ? ei[N_EDGES + e] : (e - N_EDGES);
    atomicAdd(&deg[dst], 1);
}

__global__ void degsum_kernel(const int* __restrict__ deg, int* __restrict__ bsum) {
    __shared__ int red[256];
    int b = blockIdx.x, t = threadIdx.x;
    int i = b * 256 + t;
    red[t] = (i < N_NODES) ? deg[i] : 0;
    __syncthreads();
    for (int o = 128; o; o >>= 1) { if (t < o) red[t] += red[t + o]; __syncthreads(); }
    if (t == 0) bsum[b] = red[0];
}

__global__ void scanb_kernel(const int* __restrict__ bsum, int* __restrict__ boff) {
    __shared__ int s[256];
    int t = threadIdx.x;
    int v0 = (t < NB_CSR) ? bsum[t] : 0;
    s[t] = v0;
    __syncthreads();
    for (int o = 1; o < 256; o <<= 1) {
        int v = (t >= o) ? s[t - o] : 0;
        __syncthreads();
        s[t] += v;
        __syncthreads();
    }
    if (t < NB_CSR) boff[t] = s[t] - v0;
}

__global__ void offsets_kernel(const int* __restrict__ deg, const int* __restrict__ boff,
                               int* __restrict__ off, int* __restrict__ cur) {
    __shared__ int s[256];
    int b = blockIdx.x, t = threadIdx.x;
    int i = b * 256 + t;
    int d = (i < N_NODES) ? deg[i] : 0;
    s[t] = d;
    __syncthreads();
    for (int o = 1; o < 256; o <<= 1) {
        int v = (t >= o) ? s[t - o] : 0;
        __syncthreads();
        s[t] += v;
        __syncthreads();
    }
    int excl = boff[b] + s[t] - d;
    if (i < N_NODES) { off[i] = excl; cur[i] = excl; }
    if (b == 0 && t == 0) off[N_NODES] = ETOT;
}

__global__ void scatter_kernel(const int* __restrict__ ei,
                               int* __restrict__ cur, int* __restrict__ adj) {
    int e = blockIdx.x * blockDim.x + threadIdx.x;
    if (e >= ETOT) return;
    int src, dst;
    if (e < N_EDGES) { src = ei[e]; dst = ei[N_EDGES + e]; }
    else             { src = dst = e - N_EDGES; }
    int pos = atomicAdd(&cur[dst], 1);
    adj[pos] = src;
}

// ---------------- fused GAT attention + aggregation + bias + ELU (warp per node) ----------------
__device__ __forceinline__ float lrelu(float v) { return v > 0.f ? v : 0.2f * v; }
__device__ __forceinline__ float pick4(float4 v, int h) {
    float lo = (h == 0) ? v.x : v.y;
    float hi = (h == 2) ? v.z : v.w;
    return (h < 2) ? lo : hi;
}

__global__ __launch_bounds__(256) void gat_fused_kernel(
    const int* __restrict__ off, const int* __restrict__ adj,
    const __nv_bfloat16* __restrict__ projb, const float* __restrict__ als,
    const float* __restrict__ ald, const float* __restrict__ bias,
    float* __restrict__ hout) {
    __shared__ float sE[8][CAP][4];
    __shared__ int   sS[8][CAP];
    int w = threadIdx.x >> 5, lane = threadIdx.x & 31;
    int n = blockIdx.x * 8 + w;
    if (n >= N_NODES) return;
    int e0 = off[n];
    int deg = off[n + 1] - e0;
    float4 aldn = ((const float4*)ald)[n];

    float4 mx = make_float4(-INFINITY, -INFINITY, -INFINITY, -INFINITY);
    for (int j = lane; j < deg; j += 32) {
        int s = adj[e0 + j];
        float4 a = ((const float4*)als)[s];
        float4 e;
        e.x = lrelu(a.x + aldn.x);
        e.y = lrelu(a.y + aldn.y);
        e.z = lrelu(a.z + aldn.z);
        e.w = lrelu(a.w + aldn.w);
        if (j < CAP) { sS[w][j] = s; *(float4*)sE[w][j] = e; }
        mx.x = fmaxf(mx.x, e.x); mx.y = fmaxf(mx.y, e.y);
        mx.z = fmaxf(mx.z, e.z); mx.w = fmaxf(mx.w, e.w);
    }
#pragma unroll
    for (int o = 16; o; o >>= 1) {
        mx.x = fmaxf(mx.x, __shfl_xor_sync(0xFFFFFFFFu, mx.x, o));
        mx.y = fmaxf(mx.y, __shfl_xor_sync(0xFFFFFFFFu, mx.y, o));
        mx.z = fmaxf(mx.z, __shfl_xor_sync(0xFFFFFFFFu, mx.z, o));
        mx.w = fmaxf(mx.w, __shfl_xor_sync(0xFFFFFFFFu, mx.w, o));
    }

    float4 sum = make_float4(0.f, 0.f, 0.f, 0.f);
    for (int j = lane; j < deg; j += 32) {
        float4 e;
        if (j < CAP) e = *(float4*)sE[w][j];
        else {
            int s = adj[e0 + j];
            float4 a = ((const float4*)als)[s];
            e.x = lrelu(a.x + aldn.x); e.y = lrelu(a.y + aldn.y);
            e.z = lrelu(a.z + aldn.z); e.w = lrelu(a.w + aldn.w);
        }
        float4 g;
        g.x = expf(e.x - mx.x); g.y = expf(e.y - mx.y);
        g.z = expf(e.z - mx.z); g.w = expf(e.w - mx.w);
        if (j < CAP) *(float4*)sE[w][j] = g;
        sum.x += g.x; sum.y += g.y; sum.z += g.z; sum.w += g.w;
    }
#pragma unroll
    for (int o = 16; o; o >>= 1) {
        sum.x += __shfl_xor_sync(0xFFFFFFFFu, sum.x, o);
        sum.y += __shfl_xor_sync(0xFFFFFFFFu, sum.y, o);
        sum.z += __shfl_xor_sync(0xFFFFFFFFu, sum.z, o);
        sum.w += __shfl_xor_sync(0xFFFFFFFFu, sum.w, o);
    }
    int hsel = lane >> 3;      // head for cols lane*8 .. lane*8+7
    float invh = 1.0f / (pick4(sum, hsel) + 1e-16f);
    float mxh  = pick4(mx, hsel);

    // pass 3: weighted aggregation; each lane gathers 8 bf16 cols (one uint4)
    float acc0 = 0.f, acc1 = 0.f, acc2 = 0.f, acc3 = 0.f;
    float acc4 = 0.f, acc5 = 0.f, acc6 = 0.f, acc7 = 0.f;
    for (int j = 0; j < deg; j++) {
        int s; float g;
        if (j < CAP) { s = sS[w][j]; g = sE[w][j][hsel]; }
        else {
            s = adj[e0 + j];
            float4 a = ((const float4*)als)[s];
            float eh = lrelu(pick4(a, hsel) + pick4(aldn, hsel));
            g = expf(eh - mxh);
        }
        float alpha = g * invh;
        uint4 pv = ((const uint4*)(projb + (size_t)s * DDIM))[lane];
        __nv_bfloat162 q0 = *(__nv_bfloat162*)&pv.x;
        __nv_bfloat162 q1 = *(__nv_bfloat162*)&pv.y;
        __nv_bfloat162 q2 = *(__nv_bfloat162*)&pv.z;
        __nv_bfloat162 q3 = *(__nv_bfloat162*)&pv.w;
        acc0 += alpha * __bfloat162float(q0.x); acc1 += alpha * __bfloat162float(q0.y);
        acc2 += alpha * __bfloat162float(q1.x); acc3 += alpha * __bfloat162float(q1.y);
        acc4 += alpha * __bfloat162float(q2.x); acc5 += alpha * __bfloat162float(q2.y);
        acc6 += alpha * __bfloat162float(q3.x); acc7 += alpha * __bfloat162float(q3.y);
    }

    const float4* b4 = (const float4*)bias;
    float4 b0 = b4[lane * 2], b1 = b4[lane * 2 + 1];
    float4 o0, o1;
    o0.x = acc0 + b0.x; o0.x = o0.x > 0.f ? o0.x : expm1f(o0.x);
    o0.y = acc1 + b0.y; o0.y = o0.y > 0.f ? o0.y : expm1f(o0.y);
    o0.z = acc2 + b0.z; o0.z = o0.z > 0.f ? o0.z : expm1f(o0.z);
    o0.w = acc3 + b0.w; o0.w = o0.w > 0.f ? o0.w : expm1f(o0.w);
    o1.x = acc4 + b1.x; o1.x = o1.x > 0.f ? o1.x : expm1f(o1.x);
    o1.y = acc5 + b1.y; o1.y = o1.y > 0.f ? o1.y : expm1f(o1.y);
    o1.z = acc6 + b1.z; o1.z = o1.z > 0.f ? o1.z : expm1f(o1.z);
    o1.w = acc7 + b1.w; o1.w = o1.w > 0.f ? o1.w : expm1f(o1.w);
    float4* out4 = (float4*)(hout + (size_t)n * DDIM);
    out4[lane * 2]     = o0;
    out4[lane * 2 + 1] = o1;
}

// ---------------- mean pool over sorted batch ----------------
#define PCHUNK 256
__global__ void pool_kernel(const float* __restrict__ h, const int* __restrict__ batch,
                            float* __restrict__ sums, float* __restrict__ cnt) {
    __shared__ int sb[PCHUNK];
    int n0 = blockIdx.x * PCHUNK;
    int n1 = min(N_NODES, n0 + PCHUNK);
    int cnt_local = n1 - n0;
    for (int i = threadIdx.x; i < cnt_local; i += blockDim.x) sb[i] = batch[n0 + i];
    __syncthreads();
    int t = threadIdx.x;
    float acc = 0.0f;
    int gp = sb[0];
    for (int i = 0; i < cnt_local; i++) {
        int g = sb[i];
        if (g != gp) { atomicAdd(&sums[gp * DDIM + t], acc); acc = 0.0f; gp = g; }
        acc += h[(size_t)(n0 + i) * DDIM + t];
    }
    atomicAdd(&sums[gp * DDIM + t], acc);
    if (t == 0) {
        float c = 0.0f; gp = sb[0];
        for (int i = 0; i < cnt_local; i++) {
            int g = sb[i];
            if (g != gp) { atomicAdd(&cnt[gp], c); c = 0.0f; gp = g; }
            c += 1.0f;
        }
        atomicAdd(&cnt[gp], c);
    }
}

// ---------------- decoder ----------------
__global__ void decoder_kernel(const float* __restrict__ sums, const float* __restrict__ cnt,
                               const float* __restrict__ w1, const float* __restrict__ b1,
                               const float* __restrict__ gam, const float* __restrict__ bet,
                               const float* __restrict__ w2, const float* __restrict__ b2,
                               float* __restrict__ out) {
    __shared__ float p[DDIM];
    __shared__ float y[64];
    int t = threadIdx.x;
    for (int gr = 0; gr < NGRP; gr++) {
        float invc = 1.0f / fmaxf(cnt[gr], 1.0f);
        for (int i = t; i < DDIM; i += 64) p[i] = sums[gr * DDIM + i] * invc;
        __syncthreads();
        float acc = b1[t];
        for (int k = 0; k < DDIM; k++) acc += p[k] * w1[k * 64 + t];
        y[t] = acc;
        __syncthreads();
        float m = 0.0f;
        for (int k = 0; k < 64; k++) m += y[k];
        m *= (1.0f / 64.0f);
        float v = 0.0f;
        for (int k = 0; k < 64; k++) { float d = y[k] - m; v += d * d; }
        v *= (1.0f / 64.0f);
        float z = fmaxf(0.0f, gam[t] * (acc - m) * rsqrtf(v + EPS_LN) + bet[t]);
        __syncthreads();
        y[t] = z;
        __syncthreads();
        if (t < OUTF) {
            float o = b2[t];
            for (int k = 0; k < 64; k++) o += y[k] * w2[k * OUTF + t];
            out[gr * OUTF + t] = o;
        }
        __syncthreads();
    }
}

// ---------------- orchestration ----------------
extern "C" void kernel_launch(void* const* d_in, const int* in_sizes, int n_in,
                              void* d_out, int out_size) {
    const float* x      = (const float*)d_in[0];
    const int*   ei     = (const int*)d_in[1];
    const int*   batch  = (const int*)d_in[2];
    const float* enc_w1 = (const float*)d_in[3];
    const float* enc_b1 = (const float*)d_in[4];
    const float* enc_g  = (const float*)d_in[5];
    const float* enc_be = (const float*)d_in[6];
    const float* enc_w2 = (const float*)d_in[7];
    const float* enc_b2 = (const float*)d_in[8];
    const float* convW[3]  = { (const float*)d_in[9],  (const float*)d_in[13], (const float*)d_in[17] };
    const float* convAS[3] = { (const float*)d_in[10], (const float*)d_in[14], (const float*)d_in[18] };
    const float* convAD[3] = { (const float*)d_in[11], (const float*)d_in[15], (const float*)d_in[19] };
    const float* convB[3]  = { (const float*)d_in[12], (const float*)d_in[16], (const float*)d_in[20] };
    const float* dec_w1 = (const float*)d_in[21];
    const float* dec_b1 = (const float*)d_in[22];
    const float* dec_g  = (const float*)d_in[23];
    const float* dec_be = (const float*)d_in[24];
    const float* dec_w2 = (const float*)d_in[25];
    const float* dec_b2 = (const float*)d_in[26];

    float *bufA, *bufB, *als, *ald, *sums, *cnt;
    int *deg, *off, *cur, *adj, *bsum, *boff;
    __nv_bfloat16 *wthi, *wtlo, *projb;
    cudaGetSymbolAddress((void**)&bufA,  g_bufA);
    cudaGetSymbolAddress((void**)&bufB,  g_bufB);
    cudaGetSymbolAddress((void**)&projb, g_projb);
    cudaGetSymbolAddress((void**)&als,   g_als);
    cudaGetSymbolAddress((void**)&ald,   g_ald);
    cudaGetSymbolAddress((void**)&deg,   g_deg);
    cudaGetSymbolAddress((void**)&off,   g_off);
    cudaGetSymbolAddress((void**)&cur,   g_cur);
    cudaGetSymbolAddress((void**)&adj,   g_adj);
    cudaGetSymbolAddress((void**)&sums,  g_sums);
    cudaGetSymbolAddress((void**)&cnt,   g_cnt);
    cudaGetSymbolAddress((void**)&bsum,  g_bsum);
    cudaGetSymbolAddress((void**)&boff,  g_boff);
    cudaGetSymbolAddress((void**)&wthi,  g_wthi);
    cudaGetSymbolAddress((void**)&wtlo,  g_wtlo);

    cudaFuncSetAttribute(encoder_kernel, cudaFuncAttributeMaxDynamicSharedMemorySize, ENC_SMEM);

    // CSR build
    cudaMemsetAsync(deg, 0, N_NODES * sizeof(int));
    hist_kernel<<<(ETOT + 255) / 256, 256>>>(ei, deg);
    degsum_kernel<<<NB_CSR, 256>>>(deg, bsum);
    scanb_kernel<<<1, 256>>>(bsum, boff);
    offsets_kernel<<<NB_CSR, 256>>>(deg, boff, off, cur);
    scatter_kernel<<<(ETOT + 255) / 256, 256>>>(ei, cur, adj);

    // encoder -> bufA [N,64]
    encoder_kernel<<<(N_NODES + 63) / 64, 256, ENC_SMEM>>>(
        x, enc_w1, enc_b1, enc_g, enc_be, enc_w2, enc_b2, bufA);

    float* hin = bufA;
    float* hout = bufB;
    int Fin = HID;
    for (int L = 0; L < 3; L++) {
        prep_wt_kernel<<<DDIM, 256>>>(convW[L], wthi, wtlo, Fin);
        dim3 ggrid(2, (N_NODES + 127) / 128);
        gemm_mma_kernel<<<ggrid, 256>>>(hin, wthi, wtlo, convAS[L], convAD[L],
                                        projb, als, ald, N_NODES, Fin);
        gat_fused_kernel<<<(N_NODES + 7) / 8, 256>>>(off, adj, projb, als, ald, convB[L], hout);
        float* tmp = hin; hin = hout; hout = tmp;
        Fin = DDIM;
    }

    cudaMemsetAsync(sums, 0, NGRP * DDIM * sizeof(float));
    cudaMemsetAsync(cnt, 0, NGRP * sizeof(float));
    pool_kernel<<<(N_NODES + PCHUNK - 1) / PCHUNK, 256>>>(hin, batch, sums, cnt);
    decoder_kernel<<<1, 64>>>(sums, cnt, dec_w1, dec_b1, dec_g, dec_be, dec_w2, dec_b2,
                              (float*)d_out);
}

// round 8
// speedup vs baseline: 2.7526x; 1.3103x over previous
#include <cuda_runtime.h>
#include <cuda_bf16.h>
#include <math.h>
#include <stdint.h>

#define N_NODES 50000
#define N_EDGES 800000
#define ETOT    850000   // edges + self loops
#define HID     64
#define HEADS   4
#define DDIM    256      // HID*HEADS
#define OUTF    40
#define NGRP    8
#define EPS_LN  1e-5f
#define CAP     96

// ---------------- scratch (device globals; no dynamic alloc allowed) ----------------
__device__ __nv_bfloat16 g_bufA[(size_t)N_NODES * DDIM];
__device__ __nv_bfloat16 g_bufB[(size_t)N_NODES * DDIM];
__device__ __nv_bfloat16 g_projb[(size_t)N_NODES * DDIM];
__device__ float g_als[N_NODES * HEADS];
__device__ float g_ald[N_NODES * HEADS];
__device__ int   g_deg[N_NODES];
__device__ int   g_off[N_NODES + 1];
__device__ int   g_cur[N_NODES];
__device__ int   g_adj[ETOT];
__device__ float g_sums[NGRP * DDIM];
__device__ float g_cnt[NGRP];
__device__ __nv_bfloat16 g_wthi[DDIM * DDIM];   // W^T hi, [N=256][K]
__device__ __nv_bfloat16 g_wtlo[DDIM * DDIM];   // W^T lo
#define NB_CSR ((N_NODES + 255) / 256)
__device__ int g_bsum[NB_CSR];
__device__ int g_boff[NB_CSR];

// ---------------- W prep: transpose + bf16 hi/lo split ----------------
__global__ void prep_wt_kernel(const float* __restrict__ W,
                               __nv_bfloat16* __restrict__ hi,
                               __nv_bfloat16* __restrict__ lo, int K) {
    int n = blockIdx.x;                    // 0..255
    for (int k = threadIdx.x; k < K; k += blockDim.x) {
        float v = W[(size_t)k * DDIM + n];
        __nv_bfloat16 h = __float2bfloat16(v);
        float r = v - __bfloat162float(h);
        hi[(size_t)n * K + k] = h;
        lo[(size_t)n * K + k] = __float2bfloat16(r);
    }
}

// ---------------- bf16x2 HMMA GEMM + fused attcoef + bf16 proj output ----------------
// A is bf16 [M,K]; W split hi/lo. C = A*Whi + A*Wlo in fp32 accum.
// Block: 128 (M) x 128 (N); 8 warps as 4(M) x 2(N); warp tile 32 x 64 (one head).
#define KCH 32
#define LDK 40          // padded smem row stride (bf16 elems); 80 B = 16B multiple

__device__ __forceinline__ void mma_bf16(float* c, uint32_t a0, uint32_t a1,
                                         uint32_t a2, uint32_t a3,
                                         uint32_t b0, uint32_t b1) {
    asm volatile(
        "mma.sync.aligned.m16n8k16.row.col.f32.bf16.bf16.f32 "
        "{%0,%1,%2,%3}, {%4,%5,%6,%7}, {%8,%9}, {%0,%1,%2,%3};"
        : "+f"(c[0]), "+f"(c[1]), "+f"(c[2]), "+f"(c[3])
        : "r"(a0), "r"(a1), "r"(a2), "r"(a3), "r"(b0), "r"(b1));
}

__global__ __launch_bounds__(256) void gemm_mma_kernel(
    const __nv_bfloat16* __restrict__ A,
    const __nv_bfloat16* __restrict__ BH, const __nv_bfloat16* __restrict__ BL,
    const float* __restrict__ a_s, const float* __restrict__ a_d,
    __nv_bfloat16* __restrict__ Pb,
    float* __restrict__ als, float* __restrict__ ald,
    int M, int K) {
    __shared__ __align__(16) __nv_bfloat16 sA[128][LDK];
    __shared__ __align__(16) __nv_bfloat16 sBh[128][LDK];
    __shared__ __align__(16) __nv_bfloat16 sBl[128][LDK];

    int tid = threadIdx.x;
    int warp = tid >> 5, lane = tid & 31;
    int g = lane >> 2, tg = lane & 3;
    int warpM = warp & 3, warpN = warp >> 2;   // 4 x 2
    int bm0 = blockIdx.y * 128;
    int bn0 = blockIdx.x * 128;

    float acc[2][8][4];
#pragma unroll
    for (int i = 0; i < 2; i++)
#pragma unroll
        for (int j = 0; j < 8; j++)
#pragma unroll
            for (int q = 0; q < 4; q++) acc[i][j][q] = 0.f;

    int rowLoc = tid >> 1;
    int kq = (tid & 1) * 16;    // 16 bf16 = 32 bytes = 2 x uint4 per thread
    int grow = bm0 + rowLoc;
    bool rok = grow < M;

    for (int k0 = 0; k0 < K; k0 += KCH) {
        // ---- A tile: bf16 direct, 16 bf16 (2 x uint4) per thread ----
        {
            uint4 v0 = make_uint4(0u, 0u, 0u, 0u);
            uint4 v1 = make_uint4(0u, 0u, 0u, 0u);
            if (rok) {
                const uint4* ap = (const uint4*)(A + (size_t)grow * K + k0 + kq);
                v0 = ap[0];
                v1 = ap[1];
            }
            *(uint4*)&sA[rowLoc][kq]     = v0;
            *(uint4*)&sA[rowLoc][kq + 8] = v1;
        }
        // ---- B tile: pre-split bf16 [n][k], 16 bf16 per thread each ----
        {
            const uint4* bh = (const uint4*)(BH + (size_t)(bn0 + rowLoc) * K + k0 + kq);
            const uint4* bl = (const uint4*)(BL + (size_t)(bn0 + rowLoc) * K + k0 + kq);
            *(uint4*)&sBh[rowLoc][kq]     = bh[0];
            *(uint4*)&sBh[rowLoc][kq + 8] = bh[1];
            *(uint4*)&sBl[rowLoc][kq]     = bl[0];
            *(uint4*)&sBl[rowLoc][kq + 8] = bl[1];
        }
        __syncthreads();

#pragma unroll
        for (int ks = 0; ks < 2; ks++) {
            int kb = ks * 16 + tg * 2;
            uint32_t ah[2][4];
#pragma unroll
            for (int mt = 0; mt < 2; mt++) {
                int r0 = warpM * 32 + mt * 16 + g;
                ah[mt][0] = *(const uint32_t*)&sA[r0][kb];
                ah[mt][1] = *(const uint32_t*)&sA[r0 + 8][kb];
                ah[mt][2] = *(const uint32_t*)&sA[r0][kb + 8];
                ah[mt][3] = *(const uint32_t*)&sA[r0 + 8][kb + 8];
            }
#pragma unroll
            for (int nt = 0; nt < 8; nt++) {
                int nc = warpN * 64 + nt * 8 + g;
                uint32_t bh0 = *(const uint32_t*)&sBh[nc][kb];
                uint32_t bh1 = *(const uint32_t*)&sBh[nc][kb + 8];
                uint32_t bl0 = *(const uint32_t*)&sBl[nc][kb];
                uint32_t bl1 = *(const uint32_t*)&sBl[nc][kb + 8];
#pragma unroll
                for (int mt = 0; mt < 2; mt++) {
                    mma_bf16(acc[mt][nt], ah[mt][0], ah[mt][1], ah[mt][2], ah[mt][3], bh0, bh1);
                    mma_bf16(acc[mt][nt], ah[mt][0], ah[mt][1], ah[mt][2], ah[mt][3], bl0, bl1);
                }
            }
        }
        __syncthreads();
    }

    // ---- epilogue: bf16 proj store + fused attention coefficients ----
    int head = (bn0 >> 6) + warpN;
    float asv[16], adv[16];
#pragma unroll
    for (int nt = 0; nt < 8; nt++) {
#pragma unroll
        for (int q = 0; q < 2; q++) {
            int gcol = bn0 + warpN * 64 + nt * 8 + tg * 2 + q;
            asv[nt * 2 + q] = a_s[gcol];
            adv[nt * 2 + q] = a_d[gcol];
        }
    }
#pragma unroll
    for (int mt = 0; mt < 2; mt++) {
        int r0 = bm0 + warpM * 32 + mt * 16 + g;
        float s_lo = 0.f, s_hi = 0.f, d_lo = 0.f, d_hi = 0.f;
#pragma unroll
        for (int nt = 0; nt < 8; nt++) {
            int col = bn0 + warpN * 64 + nt * 8 + tg * 2;
            __nv_bfloat162 p0 = __floats2bfloat162_rn(acc[mt][nt][0], acc[mt][nt][1]);
            __nv_bfloat162 p1 = __floats2bfloat162_rn(acc[mt][nt][2], acc[mt][nt][3]);
            if (r0 < M)     *(__nv_bfloat162*)(Pb + (size_t)r0 * DDIM + col) = p0;
            if (r0 + 8 < M) *(__nv_bfloat162*)(Pb + (size_t)(r0 + 8) * DDIM + col) = p1;
            s_lo += acc[mt][nt][0] * asv[nt * 2] + acc[mt][nt][1] * asv[nt * 2 + 1];
            s_hi += acc[mt][nt][2] * asv[nt * 2] + acc[mt][nt][3] * asv[nt * 2 + 1];
            d_lo += acc[mt][nt][0] * adv[nt * 2] + acc[mt][nt][1] * adv[nt * 2 + 1];
            d_hi += acc[mt][nt][2] * adv[nt * 2] + acc[mt][nt][3] * adv[nt * 2 + 1];
        }
#pragma unroll
        for (int o = 1; o < 4; o <<= 1) {
            s_lo += __shfl_xor_sync(0xFFFFFFFFu, s_lo, o);
            s_hi += __shfl_xor_sync(0xFFFFFFFFu, s_hi, o);
            d_lo += __shfl_xor_sync(0xFFFFFFFFu, d_lo, o);
            d_hi += __shfl_xor_sync(0xFFFFFFFFu, d_hi, o);
        }
        if (tg == 0) {
            if (r0 < M)     { als[r0 * HEADS + head] = s_lo; ald[r0 * HEADS + head] = d_lo; }
            if (r0 + 8 < M) { als[(r0 + 8) * HEADS + head] = s_hi; ald[(r0 + 8) * HEADS + head] = d_hi; }
        }
    }
}

// ---------------- encoder: 64-node tiles, weights cached in smem, bf16 out ----------------
#define ENC_SMEM ((8448 + 8192 + 4352) * 4)
__global__ __launch_bounds__(256) void encoder_kernel(
    const float* __restrict__ x,
    const float* __restrict__ w1, const float* __restrict__ b1,
    const float* __restrict__ gam, const float* __restrict__ bet,
    const float* __restrict__ w2, const float* __restrict__ b2,
    __nv_bfloat16* __restrict__ h0) {
    extern __shared__ float sm[];
    float* xs = sm;             // [64][132]
    float* ws = sm + 8448;      // [128][64] then [64][64]
    float* ys = sm + 16640;     // [64][68]
    int t = threadIdx.x;
    int n0 = blockIdx.x * 64;
    for (int i = t; i < 64 * 128; i += 256) {
        int nd = i >> 7, k = i & 127;
        int gn = n0 + nd;
        xs[nd * 132 + k] = (gn < N_NODES) ? x[(size_t)gn * 128 + k] : 0.f;
    }
    for (int i = t; i < 128 * 64; i += 256) ws[i] = w1[i];
    __syncthreads();
    int tx = t & 15, ty = t >> 4;
    float acc[4][4] = {};
#pragma unroll 4
    for (int k = 0; k < 128; k++) {
        float4 b4 = *(const float4*)&ws[k * 64 + tx * 4];
        float a0 = xs[(ty * 4 + 0) * 132 + k];
        float a1 = xs[(ty * 4 + 1) * 132 + k];
        float a2 = xs[(ty * 4 + 2) * 132 + k];
        float a3 = xs[(ty * 4 + 3) * 132 + k];
        acc[0][0] += a0 * b4.x; acc[0][1] += a0 * b4.y; acc[0][2] += a0 * b4.z; acc[0][3] += a0 * b4.w;
        acc[1][0] += a1 * b4.x; acc[1][1] += a1 * b4.y; acc[1][2] += a1 * b4.z; acc[1][3] += a1 * b4.w;
        acc[2][0] += a2 * b4.x; acc[2][1] += a2 * b4.y; acc[2][2] += a2 * b4.z; acc[2][3] += a2 * b4.w;
        acc[3][0] += a3 * b4.x; acc[3][1] += a3 * b4.y; acc[3][2] += a3 * b4.z; acc[3][3] += a3 * b4.w;
    }
    float4 b1v = *(const float4*)&b1[tx * 4];
#pragma unroll
    for (int i = 0; i < 4; i++)
        *(float4*)&ys[(ty * 4 + i) * 68 + tx * 4] = make_float4(
            acc[i][0] + b1v.x, acc[i][1] + b1v.y, acc[i][2] + b1v.z, acc[i][3] + b1v.w);
    __syncthreads();
    {
        int nd = t >> 2, q = t & 3;
        float s1 = 0.f, s2 = 0.f;
#pragma unroll
        for (int j = 0; j < 16; j++) {
            float v = ys[nd * 68 + q * 16 + j];
            s1 += v; s2 += v * v;
        }
        s1 += __shfl_xor_sync(0xFFFFFFFFu, s1, 1); s2 += __shfl_xor_sync(0xFFFFFFFFu, s2, 1);
        s1 += __shfl_xor_sync(0xFFFFFFFFu, s1, 2); s2 += __shfl_xor_sync(0xFFFFFFFFu, s2, 2);
        float m = s1 * (1.f / 64.f);
        float var = s2 * (1.f / 64.f) - m * m;
        float inv = rsqrtf(var + EPS_LN);
#pragma unroll
        for (int j = 0; j < 16; j++) {
            int col = q * 16 + j;
            float v = ys[nd * 68 + col];
            float z = gam[col] * (v - m) * inv + bet[col];
            ys[nd * 68 + col] = fmaxf(z, 0.f);
        }
    }
    __syncthreads();
    for (int i = t; i < 64 * 64; i += 256) ws[i] = w2[i];
    __syncthreads();
    float acc2[4][4] = {};
#pragma unroll 4
    for (int k = 0; k < 64; k++) {
        float4 b4 = *(const float4*)&ws[k * 64 + tx * 4];
        float a0 = ys[(ty * 4 + 0) * 68 + k];
        float a1 = ys[(ty * 4 + 1) * 68 + k];
        float a2 = ys[(ty * 4 + 2) * 68 + k];
        float a3 = ys[(ty * 4 + 3) * 68 + k];
        acc2[0][0] += a0 * b4.x; acc2[0][1] += a0 * b4.y; acc2[0][2] += a0 * b4.z; acc2[0][3] += a0 * b4.w;
        acc2[1][0] += a1 * b4.x; acc2[1][1] += a1 * b4.y; acc2[1][2] += a1 * b4.z; acc2[1][3] += a1 * b4.w;
        acc2[2][0] += a2 * b4.x; acc2[2][1] += a2 * b4.y; acc2[2][2] += a2 * b4.z; acc2[2][3] += a2 * b4.w;
        acc2[3][0] += a3 * b4.x; acc2[3][1] += a3 * b4.y; acc2[3][2] += a3 * b4.z; acc2[3][3] += a3 * b4.w;
    }
    float4 b2v = *(const float4*)&b2[tx * 4];
#pragma unroll
    for (int i = 0; i < 4; i++) {
        int gn = n0 + ty * 4 + i;
        if (gn < N_NODES) {
            __nv_bfloat162 q0 = __floats2bfloat162_rn(acc2[i][0] + b2v.x, acc2[i][1] + b2v.y);
            __nv_bfloat162 q1 = __floats2bfloat162_rn(acc2[i][2] + b2v.z, acc2[i][3] + b2v.w);
            *(__nv_bfloat162*)(h0 + (size_t)gn * 64 + tx * 4)     = q0;
            *(__nv_bfloat162*)(h0 + (size_t)gn * 64 + tx * 4 + 2) = q1;
        }
    }
}

// ---------------- CSR build (two-level scan) ----------------
__global__ void hist_kernel(const int* __restrict__ ei, int* __restrict__ deg) {
    int e = blockIdx.x * blockDim.x + threadIdx.x;
    if (e >= ETOT) return;
    int dst = (e < N_EDGES) ? ei[N_EDGES + e] : (e - N_EDGES);
    atomicAdd(&deg[dst], 1);
}

__global__ void degsum_kernel(const int* __restrict__ deg, int* __restrict__ bsum) {
    __shared__ int red[256];
    int b = blockIdx.x, t = threadIdx.x;
    int i = b * 256 + t;
    red[t] = (i < N_NODES) ? deg[i] : 0;
    __syncthreads();
    for (int o = 128; o; o >>= 1) { if (t < o) red[t] += red[t + o]; __syncthreads(); }
    if (t == 0) bsum[b] = red[0];
}

__global__ void scanb_kernel(const int* __restrict__ bsum, int* __restrict__ boff) {
    __shared__ int s[256];
    int t = threadIdx.x;
    int v0 = (t < NB_CSR) ? bsum[t] : 0;
    s[t] = v0;
    __syncthreads();
    for (int o = 1; o < 256; o <<= 1) {
        int v = (t >= o) ? s[t - o] : 0;
        __syncthreads();
        s[t] += v;
        __syncthreads();
    }
    if (t < NB_CSR) boff[t] = s[t] - v0;
}

__global__ void offsets_kernel(const int* __restrict__ deg, const int* __restrict__ boff,
                               int* __restrict__ off, int* __restrict__ cur) {
    __shared__ int s[256];
    int b = blockIdx.x, t = threadIdx.x;
    int i = b * 256 + t;
    int d = (i < N_NODES) ? deg[i] : 0;
    s[t] = d;
    __syncthreads();
    for (int o = 1; o < 256; o <<= 1) {
        int v = (t >= o) ? s[t - o] : 0;
        __syncthreads();
        s[t] += v;
        __syncthreads();
    }
    int excl = boff[b] + s[t] - d;
    if (i < N_NODES) { off[i] = excl; cur[i] = excl; }
    if (b == 0 && t == 0) off[N_NODES] = ETOT;
}

__global__ void scatter_kernel(const int* __restrict__ ei,
                               int* __restrict__ cur, int* __restrict__ adj) {
    int e = blockIdx.x * blockDim.x + threadIdx.x;
    if (e >= ETOT) return;
    int src, dst;
    if (e < N_EDGES) { src = ei[e]; dst = ei[N_EDGES + e]; }
    else             { src = dst = e - N_EDGES; }
    int pos = atomicAdd(&cur[dst], 1);
    adj[pos] = src;
}

// ---------------- fused GAT attention + aggregation + bias + ELU (warp per node) ----------------
__device__ __forceinline__ float lrelu(float v) { return v > 0.f ? v : 0.2f * v; }
__device__ __forceinline__ float pick4(float4 v, int h) {
    float lo = (h == 0) ? v.x : v.y;
    float hi = (h == 2) ? v.z : v.w;
    return (h < 2) ? lo : hi;
}

__global__ __launch_bounds__(256) void gat_fused_kernel(
    const int* __restrict__ off, const int* __restrict__ adj,
    const __nv_bfloat16* __restrict__ projb, const float* __restrict__ als,
    const float* __restrict__ ald, const float* __restrict__ bias,
    __nv_bfloat16* __restrict__ hout) {
    __shared__ float sE[8][CAP][4];
    __shared__ int   sS[8][CAP];
    int w = threadIdx.x >> 5, lane = threadIdx.x & 31;
    int n = blockIdx.x * 8 + w;
    if (n >= N_NODES) return;
    int e0 = off[n];
    int deg = off[n + 1] - e0;
    float4 aldn = ((const float4*)ald)[n];

    float4 mx = make_float4(-INFINITY, -INFINITY, -INFINITY, -INFINITY);
    for (int j = lane; j < deg; j += 32) {
        int s = adj[e0 + j];
        float4 a = ((const float4*)als)[s];
        float4 e;
        e.x = lrelu(a.x + aldn.x);
        e.y = lrelu(a.y + aldn.y);
        e.z = lrelu(a.z + aldn.z);
        e.w = lrelu(a.w + aldn.w);
        if (j < CAP) { sS[w][j] = s; *(float4*)sE[w][j] = e; }
        mx.x = fmaxf(mx.x, e.x); mx.y = fmaxf(mx.y, e.y);
        mx.z = fmaxf(mx.z, e.z); mx.w = fmaxf(mx.w, e.w);
    }
#pragma unroll
    for (int o = 16; o; o >>= 1) {
        mx.x = fmaxf(mx.x, __shfl_xor_sync(0xFFFFFFFFu, mx.x, o));
        mx.y = fmaxf(mx.y, __shfl_xor_sync(0xFFFFFFFFu, mx.y, o));
        mx.z = fmaxf(mx.z, __shfl_xor_sync(0xFFFFFFFFu, mx.z, o));
        mx.w = fmaxf(mx.w, __shfl_xor_sync(0xFFFFFFFFu, mx.w, o));
    }

    float4 sum = make_float4(0.f, 0.f, 0.f, 0.f);
    for (int j = lane; j < deg; j += 32) {
        float4 e;
        if (j < CAP) e = *(float4*)sE[w][j];
        else {
            int s = adj[e0 + j];
            float4 a = ((const float4*)als)[s];
            e.x = lrelu(a.x + aldn.x); e.y = lrelu(a.y + aldn.y);
            e.z = lrelu(a.z + aldn.z); e.w = lrelu(a.w + aldn.w);
        }
        float4 g;
        g.x = expf(e.x - mx.x); g.y = expf(e.y - mx.y);
        g.z = expf(e.z - mx.z); g.w = expf(e.w - mx.w);
        if (j < CAP) *(float4*)sE[w][j] = g;
        sum.x += g.x; sum.y += g.y; sum.z += g.z; sum.w += g.w;
    }
#pragma unroll
    for (int o = 16; o; o >>= 1) {
        sum.x += __shfl_xor_sync(0xFFFFFFFFu, sum.x, o);
        sum.y += __shfl_xor_sync(0xFFFFFFFFu, sum.y, o);
        sum.z += __shfl_xor_sync(0xFFFFFFFFu, sum.z, o);
        sum.w += __shfl_xor_sync(0xFFFFFFFFu, sum.w, o);
    }
    int hsel = lane >> 3;      // head for cols lane*8 .. lane*8+7
    float invh = 1.0f / (pick4(sum, hsel) + 1e-16f);
    float mxh  = pick4(mx, hsel);

    // pass 3: weighted aggregation, unrolled x2 for MLP
    float acc0 = 0.f, acc1 = 0.f, acc2 = 0.f, acc3 = 0.f;
    float acc4 = 0.f, acc5 = 0.f, acc6 = 0.f, acc7 = 0.f;
    int j = 0;
    for (; j + 2 <= deg; j += 2) {
        int s0, s1; float g0, g1;
        if (j < CAP) { s0 = sS[w][j]; g0 = sE[w][j][hsel]; }
        else {
            s0 = adj[e0 + j];
            float4 a = ((const float4*)als)[s0];
            g0 = expf(lrelu(pick4(a, hsel) + pick4(aldn, hsel)) - mxh);
        }
        if (j + 1 < CAP) { s1 = sS[w][j + 1]; g1 = sE[w][j + 1][hsel]; }
        else {
            s1 = adj[e0 + j + 1];
            float4 a = ((const float4*)als)[s1];
            g1 = expf(lrelu(pick4(a, hsel) + pick4(aldn, hsel)) - mxh);
        }
        uint4 p0 = ((const uint4*)(projb + (size_t)s0 * DDIM))[lane];
        uint4 p1 = ((const uint4*)(projb + (size_t)s1 * DDIM))[lane];
        float a0 = g0 * invh, a1 = g1 * invh;
        __nv_bfloat162 q;
        q = *(__nv_bfloat162*)&p0.x; acc0 += a0 * __bfloat162float(q.x); acc1 += a0 * __bfloat162float(q.y);
        q = *(__nv_bfloat162*)&p0.y; acc2 += a0 * __bfloat162float(q.x); acc3 += a0 * __bfloat162float(q.y);
        q = *(__nv_bfloat162*)&p0.z; acc4 += a0 * __bfloat162float(q.x); acc5 += a0 * __bfloat162float(q.y);
        q = *(__nv_bfloat162*)&p0.w; acc6 += a0 * __bfloat162float(q.x); acc7 += a0 * __bfloat162float(q.y);
        q = *(__nv_bfloat162*)&p1.x; acc0 += a1 * __bfloat162float(q.x); acc1 += a1 * __bfloat162float(q.y);
        q = *(__nv_bfloat162*)&p1.y; acc2 += a1 * __bfloat162float(q.x); acc3 += a1 * __bfloat162float(q.y);
        q = *(__nv_bfloat162*)&p1.z; acc4 += a1 * __bfloat162float(q.x); acc5 += a1 * __bfloat162float(q.y);
        q = *(__nv_bfloat162*)&p1.w; acc6 += a1 * __bfloat162float(q.x); acc7 += a1 * __bfloat162float(q.y);
    }
    if (j < deg) {
        int s0; float g0;
        if (j < CAP) { s0 = sS[w][j]; g0 = sE[w][j][hsel]; }
        else {
            s0 = adj[e0 + j];
            float4 a = ((const float4*)als)[s0];
            g0 = expf(lrelu(pick4(a, hsel) + pick4(aldn, hsel)) - mxh);
        }
        uint4 p0 = ((const uint4*)(projb + (size_t)s0 * DDIM))[lane];
        float a0 = g0 * invh;
        __nv_bfloat162 q;
        q = *(__nv_bfloat162*)&p0.x; acc0 += a0 * __bfloat162float(q.x); acc1 += a0 * __bfloat162float(q.y);
        q = *(__nv_bfloat162*)&p0.y; acc2 += a0 * __bfloat162float(q.x); acc3 += a0 * __bfloat162float(q.y);
        q = *(__nv_bfloat162*)&p0.z; acc4 += a0 * __bfloat162float(q.x); acc5 += a0 * __bfloat162float(q.y);
        q = *(__nv_bfloat162*)&p0.w; acc6 += a0 * __bfloat162float(q.x); acc7 += a0 * __bfloat162float(q.y);
    }

    const float4* b4 = (const float4*)bias;
    float4 b0 = b4[lane * 2], b1 = b4[lane * 2 + 1];
    float v0 = acc0 + b0.x; v0 = v0 > 0.f ? v0 : expm1f(v0);
    float v1 = acc1 + b0.y; v1 = v1 > 0.f ? v1 : expm1f(v1);
    float v2 = acc2 + b0.z; v2 = v2 > 0.f ? v2 : expm1f(v2);
    float v3 = acc3 + b0.w; v3 = v3 > 0.f ? v3 : expm1f(v3);
    float v4 = acc4 + b1.x; v4 = v4 > 0.f ? v4 : expm1f(v4);
    float v5 = acc5 + b1.y; v5 = v5 > 0.f ? v5 : expm1f(v5);
    float v6 = acc6 + b1.z; v6 = v6 > 0.f ? v6 : expm1f(v6);
    float v7 = acc7 + b1.w; v7 = v7 > 0.f ? v7 : expm1f(v7);
    uint4 ov;
    *(__nv_bfloat162*)&ov.x = __floats2bfloat162_rn(v0, v1);
    *(__nv_bfloat162*)&ov.y = __floats2bfloat162_rn(v2, v3);
    *(__nv_bfloat162*)&ov.z = __floats2bfloat162_rn(v4, v5);
    *(__nv_bfloat162*)&ov.w = __floats2bfloat162_rn(v6, v7);
    ((uint4*)(hout + (size_t)n * DDIM))[lane] = ov;
}

// ---------------- mean pool over sorted batch (bf16 input) ----------------
#define PCHUNK 256
__global__ void pool_kernel(const __nv_bfloat16* __restrict__ h, const int* __restrict__ batch,
                            float* __restrict__ sums, float* __restrict__ cnt) {
    __shared__ int sb[PCHUNK];
    int n0 = blockIdx.x * PCHUNK;
    int n1 = min(N_NODES, n0 + PCHUNK);
    int cnt_local = n1 - n0;
    for (int i = threadIdx.x; i < cnt_local; i += blockDim.x) sb[i] = batch[n0 + i];
    __syncthreads();
    int t = threadIdx.x;
    float acc = 0.0f;
    int gp = sb[0];
    for (int i = 0; i < cnt_local; i++) {
        int g = sb[i];
        if (g != gp) { atomicAdd(&sums[gp * DDIM + t], acc); acc = 0.0f; gp = g; }
        acc += __bfloat162float(h[(size_t)(n0 + i) * DDIM + t]);
    }
    atomicAdd(&sums[gp * DDIM + t], acc);
    if (t == 0) {
        float c = 0.0f; gp = sb[0];
        for (int i = 0; i < cnt_local; i++) {
            int g = sb[i];
            if (g != gp) { atomicAdd(&cnt[gp], c); c = 0.0f; gp = g; }
            c += 1.0f;
        }
        atomicAdd(&cnt[gp], c);
    }
}

// ---------------- decoder ----------------
__global__ void decoder_kernel(const float* __restrict__ sums, const float* __restrict__ cnt,
                               const float* __restrict__ w1, const float* __restrict__ b1,
                               const float* __restrict__ gam, const float* __restrict__ bet,
                               const float* __restrict__ w2, const float* __restrict__ b2,
                               float* __restrict__ out) {
    __shared__ float p[DDIM];
    __shared__ float y[64];
    int t = threadIdx.x;
    for (int gr = 0; gr < NGRP; gr++) {
        float invc = 1.0f / fmaxf(cnt[gr], 1.0f);
        for (int i = t; i < DDIM; i += 64) p[i] = sums[gr * DDIM + i] * invc;
        __syncthreads();
        float acc = b1[t];
        for (int k = 0; k < DDIM; k++) acc += p[k] * w1[k * 64 + t];
        y[t] = acc;
        __syncthreads();
        float m = 0.0f;
        for (int k = 0; k < 64; k++) m += y[k];
        m *= (1.0f / 64.0f);
        float v = 0.0f;
        for (int k = 0; k < 64; k++) { float d = y[k] - m; v += d * d; }
        v *= (1.0f / 64.0f);
        float z = fmaxf(0.0f, gam[t] * (acc - m) * rsqrtf(v + EPS_LN) + bet[t]);
        __syncthreads();
        y[t] = z;
        __syncthreads();
        if (t < OUTF) {
            float o = b2[t];
            for (int k = 0; k < 64; k++) o += y[k] * w2[k * OUTF + t];
            out[gr * OUTF + t] = o;
        }
        __syncthreads();
    }
}

// ---------------- orchestration ----------------
extern "C" void kernel_launch(void* const* d_in, const int* in_sizes, int n_in,
                              void* d_out, int out_size) {
    const float* x      = (const float*)d_in[0];
    const int*   ei     = (const int*)d_in[1];
    const int*   batch  = (const int*)d_in[2];
    const float* enc_w1 = (const float*)d_in[3];
    const float* enc_b1 = (const float*)d_in[4];
    const float* enc_g  = (const float*)d_in[5];
    const float* enc_be = (const float*)d_in[6];
    const float* enc_w2 = (const float*)d_in[7];
    const float* enc_b2 = (const float*)d_in[8];
    const float* convW[3]  = { (const float*)d_in[9],  (const float*)d_in[13], (const float*)d_in[17] };
    const float* convAS[3] = { (const float*)d_in[10], (const float*)d_in[14], (const float*)d_in[18] };
    const float* convAD[3] = { (const float*)d_in[11], (const float*)d_in[15], (const float*)d_in[19] };
    const float* convB[3]  = { (const float*)d_in[12], (const float*)d_in[16], (const float*)d_in[20] };
    const float* dec_w1 = (const float*)d_in[21];
    const float* dec_b1 = (const float*)d_in[22];
    const float* dec_g  = (const float*)d_in[23];
    const float* dec_be = (const float*)d_in[24];
    const float* dec_w2 = (const float*)d_in[25];
    const float* dec_b2 = (const float*)d_in[26];

    float *als, *ald, *sums, *cnt;
    int *deg, *off, *cur, *adj, *bsum, *boff;
    __nv_bfloat16 *wthi, *wtlo, *projb, *bufA, *bufB;
    cudaGetSymbolAddress((void**)&bufA,  g_bufA);
    cudaGetSymbolAddress((void**)&bufB,  g_bufB);
    cudaGetSymbolAddress((void**)&projb, g_projb);
    cudaGetSymbolAddress((void**)&als,   g_als);
    cudaGetSymbolAddress((void**)&ald,   g_ald);
    cudaGetSymbolAddress((void**)&deg,   g_deg);
    cudaGetSymbolAddress((void**)&off,   g_off);
    cudaGetSymbolAddress((void**)&cur,   g_cur);
    cudaGetSymbolAddress((void**)&adj,   g_adj);
    cudaGetSymbolAddress((void**)&sums,  g_sums);
    cudaGetSymbolAddress((void**)&cnt,   g_cnt);
    cudaGetSymbolAddress((void**)&bsum,  g_bsum);
    cudaGetSymbolAddress((void**)&boff,  g_boff);
    cudaGetSymbolAddress((void**)&wthi,  g_wthi);
    cudaGetSymbolAddress((void**)&wtlo,  g_wtlo);

    cudaFuncSetAttribute(encoder_kernel, cudaFuncAttributeMaxDynamicSharedMemorySize, ENC_SMEM);

    // CSR build
    cudaMemsetAsync(deg, 0, N_NODES * sizeof(int));
    hist_kernel<<<(ETOT + 255) / 256, 256>>>(ei, deg);
    degsum_kernel<<<NB_CSR, 256>>>(deg, bsum);
    scanb_kernel<<<1, 256>>>(bsum, boff);
    offsets_kernel<<<NB_CSR, 256>>>(deg, boff, off, cur);
    scatter_kernel<<<(ETOT + 255) / 256, 256>>>(ei, cur, adj);

    // encoder -> bufA [N,64] bf16
    encoder_kernel<<<(N_NODES + 63) / 64, 256, ENC_SMEM>>>(
        x, enc_w1, enc_b1, enc_g, enc_be, enc_w2, enc_b2, bufA);

    __nv_bfloat16* hin = bufA;
    __nv_bfloat16* hout = bufB;
    int Fin = HID;
    for (int L = 0; L < 3; L++) {
        prep_wt_kernel<<<DDIM, 256>>>(convW[L], wthi, wtlo, Fin);
        dim3 ggrid(2, (N_NODES + 127) / 128);
        gemm_mma_kernel<<<ggrid, 256>>>(hin, wthi, wtlo, convAS[L], convAD[L],
                                        projb, als, ald, N_NODES, Fin);
        gat_fused_kernel<<<(N_NODES + 7) / 8, 256>>>(off, adj, projb, als, ald, convB[L], hout);
        __nv_bfloat16* tmp = hin; hin = hout; hout = tmp;
        Fin = DDIM;
    }

    cudaMemsetAsync(sums, 0, NGRP * DDIM * sizeof(float));
    cudaMemsetAsync(cnt, 0, NGRP * sizeof(float));
    pool_kernel<<<(N_NODES + PCHUNK - 1) / PCHUNK, 256>>>(hin, batch, sums, cnt);
    decoder_kernel<<<1, 64>>>(sums, cnt, dec_w1, dec_b1, dec_g, dec_be, dec_w2, dec_b2,
                              (float*)d_out);
}